// round 1
// baseline (speedup 1.0000x reference)
#include <cuda_runtime.h>
#include <math.h>

// ---------------------------------------------------------------------------
// TeleChat2 attention block, fp32 baseline (R0).
// Pipeline: QKV GEMMs -> RoPE (+ K/V transpose to [B,KV,S,D]) -> flash attn
//           (64x64 tiles, online softmax) -> output GEMM + bias.
// ---------------------------------------------------------------------------

static constexpr int Bb  = 2;
static constexpr int Ss  = 2048;
static constexpr int HID = 4096;
static constexpr int NH  = 32;
static constexpr int NKV = 8;
static constexpr int HD  = 128;
static constexpr int M_TOK = Bb * Ss;          // 4096 token rows
static constexpr int KVW   = 2 * NKV * HD;     // 2048

// Scratch (static device globals — no runtime allocation).
__device__ float g_Q   [(size_t)M_TOK * HID];      // roped Q, token-major [b,s,h,d]
__device__ float g_KV  [(size_t)M_TOK * KVW];      // raw KV projection
__device__ float g_K   [(size_t)Bb * NKV * Ss * HD]; // roped K, [b,kv,s,d]
__device__ float g_V   [(size_t)Bb * NKV * Ss * HD]; // V,       [b,kv,s,d]
__device__ float g_attn[(size_t)M_TOK * HID];      // attention output, token-major

// ---------------------------------------------------------------------------
// SGEMM: C[m,n] = sum_k A[m,k] * W[n,k] (+ bias[n]).  A:[M,K] row-major,
// W:[N,K] row-major (i.e. C = A @ W^T).  128x128 block, 8x8 per thread,
// BK=16, 256 threads.  M,N,K multiples of 128/16 (true for all calls here).
// ---------------------------------------------------------------------------
__global__ __launch_bounds__(256) void sgemm_nt_kernel(
    const float* __restrict__ A, const float* __restrict__ W,
    const float* __restrict__ bias, float* __restrict__ C,
    int M, int N, int K)
{
    __shared__ float As[16][128];
    __shared__ float Ws[16][128];

    const int bm = blockIdx.y * 128;
    const int bn = blockIdx.x * 128;
    const int tid = threadIdx.x;
    const int tx = tid & 15;        // 0..15
    const int ty = tid >> 4;        // 0..15
    const int lrow = tid >> 2;      // 0..63
    const int lc   = (tid & 3) << 2; // 0,4,8,12

    float acc[8][8];
#pragma unroll
    for (int i = 0; i < 8; i++)
#pragma unroll
        for (int j = 0; j < 8; j++) acc[i][j] = 0.0f;

    const float* Aptr = A + (size_t)(bm + lrow) * K + lc;
    const float* Wptr = W + (size_t)(bn + lrow) * K + lc;

    for (int k0 = 0; k0 < K; k0 += 16) {
        float4 a0 = *(const float4*)(Aptr + k0);
        float4 a1 = *(const float4*)(Aptr + (size_t)64 * K + k0);
        float4 w0 = *(const float4*)(Wptr + k0);
        float4 w1 = *(const float4*)(Wptr + (size_t)64 * K + k0);

        __syncthreads();   // previous tile's compute must finish
        As[lc + 0][lrow] = a0.x; As[lc + 1][lrow] = a0.y;
        As[lc + 2][lrow] = a0.z; As[lc + 3][lrow] = a0.w;
        As[lc + 0][lrow + 64] = a1.x; As[lc + 1][lrow + 64] = a1.y;
        As[lc + 2][lrow + 64] = a1.z; As[lc + 3][lrow + 64] = a1.w;
        Ws[lc + 0][lrow] = w0.x; Ws[lc + 1][lrow] = w0.y;
        Ws[lc + 2][lrow] = w0.z; Ws[lc + 3][lrow] = w0.w;
        Ws[lc + 0][lrow + 64] = w1.x; Ws[lc + 1][lrow + 64] = w1.y;
        Ws[lc + 2][lrow + 64] = w1.z; Ws[lc + 3][lrow + 64] = w1.w;
        __syncthreads();

#pragma unroll
        for (int kk = 0; kk < 16; kk++) {
            float4 av0 = *(const float4*)&As[kk][ty * 4];
            float4 av1 = *(const float4*)&As[kk][64 + ty * 4];
            float4 bv0 = *(const float4*)&Ws[kk][tx * 4];
            float4 bv1 = *(const float4*)&Ws[kk][64 + tx * 4];
            float ar[8] = {av0.x, av0.y, av0.z, av0.w, av1.x, av1.y, av1.z, av1.w};
            float br[8] = {bv0.x, bv0.y, bv0.z, bv0.w, bv1.x, bv1.y, bv1.z, bv1.w};
#pragma unroll
            for (int i = 0; i < 8; i++)
#pragma unroll
                for (int j = 0; j < 8; j++)
                    acc[i][j] = fmaf(ar[i], br[j], acc[i][j]);
        }
    }

#pragma unroll
    for (int i = 0; i < 8; i++) {
        int row = bm + ((i < 4) ? (ty * 4 + i) : (64 + ty * 4 + (i - 4)));
        float4 o0 = make_float4(acc[i][0], acc[i][1], acc[i][2], acc[i][3]);
        float4 o1 = make_float4(acc[i][4], acc[i][5], acc[i][6], acc[i][7]);
        int c0 = bn + tx * 4;
        int c1 = bn + 64 + tx * 4;
        if (bias) {
            o0.x += bias[c0 + 0]; o0.y += bias[c0 + 1];
            o0.z += bias[c0 + 2]; o0.w += bias[c0 + 3];
            o1.x += bias[c1 + 0]; o1.y += bias[c1 + 1];
            o1.z += bias[c1 + 2]; o1.w += bias[c1 + 3];
        }
        *(float4*)(C + (size_t)row * N + c0) = o0;
        *(float4*)(C + (size_t)row * N + c1) = o1;
    }
}

// ---------------------------------------------------------------------------
// RoPE on Q (in place, token-major [b,s,h,d]).
// q'[d]    = q[d]*cos[s,d]    - q[d+64]*sin[s,d]
// q'[d+64] = q[d+64]*cos[s,d+64] + q[d]*sin[s,d+64]
// ---------------------------------------------------------------------------
__global__ __launch_bounds__(256) void rope_q_kernel(
    float* __restrict__ Q, const float* __restrict__ cosT,
    const float* __restrict__ sinT)
{
    const int row = blockIdx.x;          // b*S + s
    const int s = row & (Ss - 1);
    float* qrow = Q + (size_t)row * HID;
    const float* cr = cosT + (size_t)s * HD;
    const float* sr = sinT + (size_t)s * HD;
    for (int p = threadIdx.x; p < NH * 64; p += blockDim.x) {
        const int h = p >> 6;
        const int d = p & 63;
        float* q = qrow + h * HD;
        float lo = q[d], hi = q[d + 64];
        q[d]      = lo * cr[d]      - hi * sr[d];
        q[d + 64] = hi * cr[d + 64] + lo * sr[d + 64];
    }
}

// ---------------------------------------------------------------------------
// RoPE on K + transpose K,V from token-major KV [b,s,kv,(k|v)128] into
// [b, kv, s, d] layouts for the attention kernel.
// ---------------------------------------------------------------------------
__global__ __launch_bounds__(256) void rope_kv_kernel(
    const float* __restrict__ KV, const float* __restrict__ cosT,
    const float* __restrict__ sinT, float* __restrict__ Kout,
    float* __restrict__ Vout)
{
    const int row = blockIdx.x;          // b*S + s
    const int bq = row >> 11;            // /Ss
    const int s = row & (Ss - 1);
    const float* kvrow = KV + (size_t)row * KVW;
    const float* cr = cosT + (size_t)s * HD;
    const float* sr = sinT + (size_t)s * HD;
    for (int p = threadIdx.x; p < NKV * 64; p += blockDim.x) {
        const int kv = p >> 6;
        const int d = p & 63;
        const float* k = kvrow + kv * (2 * HD);
        const float* v = k + HD;
        float lo = k[d], hi = k[d + 64];
        size_t obase = ((size_t)(bq * NKV + kv) * Ss + s) * HD;
        Kout[obase + d]      = lo * cr[d]      - hi * sr[d];
        Kout[obase + d + 64] = hi * cr[d + 64] + lo * sr[d + 64];
        Vout[obase + d]      = v[d];
        Vout[obase + d + 64] = v[d + 64];
    }
}

// ---------------------------------------------------------------------------
// Flash attention, fp32.  Grid (S/64, NH, B), 256 threads.
// 64 q-rows per block, K/V tiles of 64, online softmax, causal tile skip.
// Thread (ty,tx) 16x16: owns S[ty*4..+3][tx*4..+3] and O rows ty*4..+3 over
// d columns {tx*4..+3, 64+tx*4..+3}.
// smem strides chosen for low bank conflicts: Q/K 129, V 132 (16B-aligned
// float4 reads), P 65.
// ---------------------------------------------------------------------------
static constexpr int QS_STR = 129;
static constexpr int VS_STR = 132;
static constexpr int PS_STR = 65;
static constexpr int ATTN_SMEM_FLOATS = 64 * QS_STR * 2 + 64 * VS_STR + 64 * PS_STR;

__global__ __launch_bounds__(256) void flash_attn_kernel(
    const float* __restrict__ Q, const float* __restrict__ Kg,
    const float* __restrict__ Vg, float* __restrict__ Out)
{
    const int qt = blockIdx.x;
    const int h  = blockIdx.y;
    const int b  = blockIdx.z;
    const int kvh = h >> 2;              // n_rep = 4

    extern __shared__ float sm[];
    float* Qs = sm;                       // [64][129]
    float* Ks = Qs + 64 * QS_STR;         // [64][129]
    float* Vs = Ks + 64 * QS_STR;         // [64][132]
    float* Ps = Vs + 64 * VS_STR;         // [64][65]

    const int tid = threadIdx.x;
    const int tx = tid & 15;
    const int ty = tid >> 4;
    const float scale = 0.08838834764831845f; // 1/sqrt(128)

    // Load + scale Q tile
    {
        const float* qbase = Q + ((size_t)(b * Ss + qt * 64)) * HID + h * HD;
        for (int idx = tid; idx < 64 * 32; idx += 256) {
            int r = idx >> 5;
            int c = (idx & 31) << 2;
            float4 v = *(const float4*)(qbase + (size_t)r * HID + c);
            float* dst = Qs + r * QS_STR + c;
            dst[0] = v.x * scale; dst[1] = v.y * scale;
            dst[2] = v.z * scale; dst[3] = v.w * scale;
        }
    }

    float mrow[4], lrow[4], o[4][8];
#pragma unroll
    for (int i = 0; i < 4; i++) {
        mrow[i] = -1e30f; lrow[i] = 0.0f;
#pragma unroll
        for (int j = 0; j < 8; j++) o[i][j] = 0.0f;
    }
    __syncthreads();

    const float* kbase0 = Kg + ((size_t)(b * NKV + kvh) * Ss) * HD;
    const float* vbase0 = Vg + ((size_t)(b * NKV + kvh) * Ss) * HD;

    for (int kt = 0; kt <= qt; kt++) {
        // Load K,V tiles
        const float* kbase = kbase0 + (size_t)(kt * 64) * HD;
        const float* vbase = vbase0 + (size_t)(kt * 64) * HD;
        for (int idx = tid; idx < 64 * 32; idx += 256) {
            int r = idx >> 5;
            int c = (idx & 31) << 2;
            float4 kv4 = *(const float4*)(kbase + (size_t)r * HD + c);
            float* kd = Ks + r * QS_STR + c;
            kd[0] = kv4.x; kd[1] = kv4.y; kd[2] = kv4.z; kd[3] = kv4.w;
            float4 vv4 = *(const float4*)(vbase + (size_t)r * HD + c);
            *(float4*)(Vs + r * VS_STR + c) = vv4;
        }
        __syncthreads();

        // S = Qs * Ks^T (4x4 per thread)
        float sacc[4][4];
#pragma unroll
        for (int i = 0; i < 4; i++)
#pragma unroll
            for (int j = 0; j < 4; j++) sacc[i][j] = 0.0f;

#pragma unroll 4
        for (int d = 0; d < HD; d++) {
            float ar[4], br[4];
#pragma unroll
            for (int i = 0; i < 4; i++) ar[i] = Qs[(ty * 4 + i) * QS_STR + d];
#pragma unroll
            for (int j = 0; j < 4; j++) br[j] = Ks[(tx * 4 + j) * QS_STR + d];
#pragma unroll
            for (int i = 0; i < 4; i++)
#pragma unroll
                for (int j = 0; j < 4; j++)
                    sacc[i][j] = fmaf(ar[i], br[j], sacc[i][j]);
        }

        // Causal mask on the diagonal tile
        if (kt == qt) {
#pragma unroll
            for (int i = 0; i < 4; i++)
#pragma unroll
                for (int j = 0; j < 4; j++)
                    if (tx * 4 + j > ty * 4 + i) sacc[i][j] = -1e30f;
        }

        // Online softmax per q-row (reduce across the 16 tx lanes)
#pragma unroll
        for (int i = 0; i < 4; i++) {
            float mloc = fmaxf(fmaxf(sacc[i][0], sacc[i][1]),
                               fmaxf(sacc[i][2], sacc[i][3]));
#pragma unroll
            for (int off = 8; off >= 1; off >>= 1)
                mloc = fmaxf(mloc, __shfl_xor_sync(0xffffffffu, mloc, off));
            float mnew = fmaxf(mrow[i], mloc);
            float ls = 0.0f;
#pragma unroll
            for (int j = 0; j < 4; j++) {
                float p = __expf(sacc[i][j] - mnew);
                ls += p;
                Ps[(ty * 4 + i) * PS_STR + tx * 4 + j] = p;
            }
#pragma unroll
            for (int off = 8; off >= 1; off >>= 1)
                ls += __shfl_xor_sync(0xffffffffu, ls, off);
            float fac = __expf(mrow[i] - mnew);
            lrow[i] = lrow[i] * fac + ls;
            mrow[i] = mnew;
#pragma unroll
            for (int j = 0; j < 8; j++) o[i][j] *= fac;
        }
        __syncthreads();

        // O += P * V
#pragma unroll 2
        for (int kj = 0; kj < 64; kj++) {
            float pv[4];
#pragma unroll
            for (int i = 0; i < 4; i++) pv[i] = Ps[(ty * 4 + i) * PS_STR + kj];
            float4 v0 = *(const float4*)&Vs[kj * VS_STR + tx * 4];
            float4 v1 = *(const float4*)&Vs[kj * VS_STR + 64 + tx * 4];
            float vr[8] = {v0.x, v0.y, v0.z, v0.w, v1.x, v1.y, v1.z, v1.w};
#pragma unroll
            for (int i = 0; i < 4; i++)
#pragma unroll
                for (int j = 0; j < 8; j++)
                    o[i][j] = fmaf(pv[i], vr[j], o[i][j]);
        }
        __syncthreads();
    }

    // Normalize + write out (token-major [b,s,h,d])
#pragma unroll
    for (int i = 0; i < 4; i++) {
        float inv = 1.0f / lrow[i];
        int qg = qt * 64 + ty * 4 + i;
        float* optr = Out + ((size_t)(b * Ss + qg)) * HID + h * HD;
        float4 o0 = make_float4(o[i][0] * inv, o[i][1] * inv, o[i][2] * inv, o[i][3] * inv);
        float4 o1 = make_float4(o[i][4] * inv, o[i][5] * inv, o[i][6] * inv, o[i][7] * inv);
        *(float4*)(optr + tx * 4) = o0;
        *(float4*)(optr + 64 + tx * 4) = o1;
    }
}

// ---------------------------------------------------------------------------
// Launch
// ---------------------------------------------------------------------------
extern "C" void kernel_launch(void* const* d_in, const int* in_sizes, int n_in,
                              void* d_out, int out_size)
{
    const float* hidden = (const float*)d_in[0];
    // d_in[1] attention_mask: pure causal -1e9, implemented directly.
    const float* cosT = (const float*)d_in[2];
    const float* sinT = (const float*)d_in[3];
    const float* Wq   = (const float*)d_in[4];
    const float* Wkv  = (const float*)d_in[5];
    const float* Wd   = (const float*)d_in[6];
    const float* bd   = (const float*)d_in[7];
    float* out = (float*)d_out;

    float *Qb, *KVb, *Kb, *Vb, *Ab;
    cudaGetSymbolAddress((void**)&Qb,  g_Q);
    cudaGetSymbolAddress((void**)&KVb, g_KV);
    cudaGetSymbolAddress((void**)&Kb,  g_K);
    cudaGetSymbolAddress((void**)&Vb,  g_V);
    cudaGetSymbolAddress((void**)&Ab,  g_attn);

    // Q and KV projections
    sgemm_nt_kernel<<<dim3(HID / 128, M_TOK / 128), 256>>>(
        hidden, Wq, nullptr, Qb, M_TOK, HID, HID);
    sgemm_nt_kernel<<<dim3(KVW / 128, M_TOK / 128), 256>>>(
        hidden, Wkv, nullptr, KVb, M_TOK, KVW, HID);

    // RoPE + K/V transpose
    rope_q_kernel<<<M_TOK, 256>>>(Qb, cosT, sinT);
    rope_kv_kernel<<<M_TOK, 256>>>(KVb, cosT, sinT, Kb, Vb);

    // Flash attention
    size_t smem_bytes = (size_t)ATTN_SMEM_FLOATS * sizeof(float);
    cudaFuncSetAttribute(flash_attn_kernel,
                         cudaFuncAttributeMaxDynamicSharedMemorySize,
                         (int)smem_bytes);
    flash_attn_kernel<<<dim3(Ss / 64, NH, Bb), 256, smem_bytes>>>(Qb, Kb, Vb, Ab);

    // Output projection + bias
    sgemm_nt_kernel<<<dim3(HID / 128, M_TOK / 128), 256>>>(
        Ab, Wd, bd, out, M_TOK, HID, HID);
}

// round 4
// speedup vs baseline: 1.8584x; 1.8584x over previous
#include <cuda_runtime.h>
#include <cuda_bf16.h>
#include <math.h>
#include <stdint.h>

// ---------------------------------------------------------------------------
// TeleChat2 attention block, R3: projection GEMMs on tensor cores via
// mma.sync bf16 (3-pass hi/lo split of fp32), cp.async double buffering.
// (tcgen05 PTX is rejected: harness compiles with target sm_103, which only
//  accepts baseline sm_80-era tensor instructions.)
// ---------------------------------------------------------------------------

static constexpr int Bb  = 2;
static constexpr int Ss  = 2048;
static constexpr int HID = 4096;
static constexpr int NH  = 32;
static constexpr int NKV = 8;
static constexpr int HD  = 128;
static constexpr int M_TOK = Bb * Ss;          // 4096 token rows
static constexpr int KVW   = 2 * NKV * HD;     // 2048

// fp32 scratch
__device__ float g_Q   [(size_t)M_TOK * HID];
__device__ float g_KV  [(size_t)M_TOK * KVW];
__device__ float g_K   [(size_t)Bb * NKV * Ss * HD];
__device__ float g_V   [(size_t)Bb * NKV * Ss * HD];
__device__ float g_attn[(size_t)M_TOK * HID];

// bf16 hi/lo split scratch
__device__ __nv_bfloat16 g_hid_hi[(size_t)M_TOK * HID];
__device__ __nv_bfloat16 g_hid_lo[(size_t)M_TOK * HID];
__device__ __nv_bfloat16 g_Wq_hi [(size_t)HID * HID];
__device__ __nv_bfloat16 g_Wq_lo [(size_t)HID * HID];
__device__ __nv_bfloat16 g_Wkv_hi[(size_t)KVW * HID];
__device__ __nv_bfloat16 g_Wkv_lo[(size_t)KVW * HID];
__device__ __nv_bfloat16 g_Wd_hi [(size_t)HID * HID];
__device__ __nv_bfloat16 g_Wd_lo [(size_t)HID * HID];
__device__ __nv_bfloat16 g_at_hi [(size_t)M_TOK * HID];
__device__ __nv_bfloat16 g_at_lo [(size_t)M_TOK * HID];

// ---------------------------------------------------------------------------
// helpers
// ---------------------------------------------------------------------------
__device__ __forceinline__ uint32_t smem_u32(const void* p) {
    uint32_t a;
    asm("{ .reg .u64 t; cvta.to.shared.u64 t, %1; cvt.u32.u64 %0, t; }"
        : "=r"(a) : "l"(p));
    return a;
}

// 16B-unit XOR swizzle: tile rows are 64B (4 chunks of 16B) logically, stored
// as 128B superrows (2 rows each). Conflict-free for ldmatrix 8-row phases.
__device__ __forceinline__ uint32_t sw_off(int row, int chunk) {
    int unit = ((row & 1) * 4 + chunk) ^ ((row >> 1) & 7);
    return (uint32_t)((row >> 1) * 128 + unit * 16);
}

#define LDSM_X4(r, addr) \
    asm volatile("ldmatrix.sync.aligned.m8n8.x4.shared.b16 {%0,%1,%2,%3}, [%4];" \
        : "=r"((r)[0]), "=r"((r)[1]), "=r"((r)[2]), "=r"((r)[3]) : "r"(addr))

#define MMA_BF16(c, a, b0v, b1v) \
    asm volatile("mma.sync.aligned.m16n8k16.row.col.f32.bf16.bf16.f32 " \
        "{%0,%1,%2,%3}, {%4,%5,%6,%7}, {%8,%9}, {%0,%1,%2,%3};" \
        : "+f"((c)[0]), "+f"((c)[1]), "+f"((c)[2]), "+f"((c)[3]) \
        : "r"((a)[0]), "r"((a)[1]), "r"((a)[2]), "r"((a)[3]), "r"(b0v), "r"(b1v))

#define CP_ASYNC16(saddr, gptr) \
    asm volatile("cp.async.cg.shared.global [%0], [%1], 16;" \
        :: "r"(saddr), "l"(gptr) : "memory")
#define CP_COMMIT() asm volatile("cp.async.commit_group;" ::: "memory")
#define CP_WAIT(n)  asm volatile("cp.async.wait_group %0;" :: "n"(n) : "memory")

// ---------------------------------------------------------------------------
// fp32 -> (hi, lo) bf16 split: hi = bf16(x), lo = bf16(x - float(hi))
// ---------------------------------------------------------------------------
__global__ __launch_bounds__(256) void split_bf16_kernel(
    const float* __restrict__ in, __nv_bfloat16* __restrict__ hi,
    __nv_bfloat16* __restrict__ lo, int n4)
{
    int i = blockIdx.x * blockDim.x + threadIdx.x;
    int stride = gridDim.x * blockDim.x;
    const float4* in4 = (const float4*)in;
    __nv_bfloat162* h2 = (__nv_bfloat162*)hi;
    __nv_bfloat162* l2 = (__nv_bfloat162*)lo;
    for (; i < n4; i += stride) {
        float4 v = in4[i];
        __nv_bfloat16 hx = __float2bfloat16(v.x);
        __nv_bfloat16 hy = __float2bfloat16(v.y);
        __nv_bfloat16 hz = __float2bfloat16(v.z);
        __nv_bfloat16 hw = __float2bfloat16(v.w);
        __nv_bfloat16 lx = __float2bfloat16(v.x - __bfloat162float(hx));
        __nv_bfloat16 ly = __float2bfloat16(v.y - __bfloat162float(hy));
        __nv_bfloat16 lz = __float2bfloat16(v.z - __bfloat162float(hz));
        __nv_bfloat16 lw = __float2bfloat16(v.w - __bfloat162float(hw));
        h2[2 * i]     = __nv_bfloat162(hx, hy);
        h2[2 * i + 1] = __nv_bfloat162(hz, hw);
        l2[2 * i]     = __nv_bfloat162(lx, ly);
        l2[2 * i + 1] = __nv_bfloat162(lz, lw);
    }
}

// ---------------------------------------------------------------------------
// Tensor-core GEMM: C[m,n] = sum_k A[m,k]*W[n,k] (+bias), bf16 3-pass split.
// CTA tile 128x128, BK=32, 256 threads = 8 warps (2 m x 4 n), warp 64x32.
// cp.async double-buffered smem (4 tiles/stage: Ah, Al, Bh, Bl; 8KB each).
// ---------------------------------------------------------------------------
static constexpr int GT = 8192;                 // tile bytes (128 rows x 64B)
static constexpr int GSTAGE = 4 * GT;           // 32 KB
static constexpr int GEMM_SMEM = 2 * GSTAGE;    // 64 KB

__global__ __launch_bounds__(256) void gemm_mma_kernel(
    const __nv_bfloat16* __restrict__ Ah, const __nv_bfloat16* __restrict__ Al,
    const __nv_bfloat16* __restrict__ Bh, const __nv_bfloat16* __restrict__ Bl,
    const float* __restrict__ bias, float* __restrict__ C,
    int M, int N, int K)
{
    extern __shared__ char smem[];
    const uint32_t sb = smem_u32(smem);
    const int tid  = threadIdx.x;
    const int wid  = tid >> 5;
    const int lane = tid & 31;
    const int bm = blockIdx.y * 128;
    const int bn = blockIdx.x * 128;
    const int m0 = (wid >> 2) * 64;   // warp row offset in tile
    const int n0 = (wid & 3) * 32;    // warp col offset in tile

    float acc[4][4][4];
#pragma unroll
    for (int i = 0; i < 4; i++)
#pragma unroll
        for (int j = 0; j < 4; j++)
#pragma unroll
            for (int r = 0; r < 4; r++) acc[i][j][r] = 0.0f;

    const int nchunk = K >> 5;

    // ---- stage loader: 2048 x 16B cp.async, 8 per thread ----
    auto load_stage = [&](int c, int stage) {
        const int k0 = c << 5;
        const uint32_t sbase = sb + stage * GSTAGE;
#pragma unroll
        for (int t = 0; t < 8; t++) {
            int op   = tid + t * 256;
            int tile = op >> 9;          // 0 Ah, 1 Al, 2 Bh, 3 Bl
            int idx  = op & 511;
            int row  = idx >> 2;
            int ch   = idx & 3;
            const __nv_bfloat16* src =
                (tile == 0) ? Ah : (tile == 1) ? Al : (tile == 2) ? Bh : Bl;
            int grow = ((tile < 2) ? bm : bn) + row;
            const void* g = src + (size_t)grow * K + k0 + ch * 8;
            uint32_t saddr = sbase + (uint32_t)tile * GT + sw_off(row, ch);
            CP_ASYNC16(saddr, g);
        }
        CP_COMMIT();
    };

    // fragment addressing (lane-constant parts)
    const int rA = ((lane >> 3) & 1) * 8 + (lane & 7);
    const int cA = (lane >> 4);               // + 2*s
    const int rB = ((lane >> 4) & 1) * 8 + (lane & 7);
    const int cB = ((lane >> 3) & 1);         // + 2*s

    load_stage(0, 0);

    for (int c = 0; c < nchunk; c++) {
        if (c + 1 < nchunk) { load_stage(c + 1, (c + 1) & 1); CP_WAIT(1); }
        else                { CP_WAIT(0); }
        __syncthreads();

        const uint32_t sbase = sb + (c & 1) * GSTAGE;
#pragma unroll
        for (int s = 0; s < 2; s++) {
            uint32_t ahf[4][4], alf[4][4], bhf[2][4], blf[2][4];
#pragma unroll
            for (int i = 0; i < 4; i++) {
                uint32_t off = sw_off(m0 + i * 16 + rA, 2 * s + cA);
                LDSM_X4(ahf[i], sbase + off);
                LDSM_X4(alf[i], sbase + GT + off);
            }
#pragma unroll
            for (int j2 = 0; j2 < 2; j2++) {
                uint32_t off = sw_off(n0 + j2 * 16 + rB, 2 * s + cB);
                LDSM_X4(bhf[j2], sbase + 2 * GT + off);
                LDSM_X4(blf[j2], sbase + 3 * GT + off);
            }
#pragma unroll
            for (int i = 0; i < 4; i++)
#pragma unroll
                for (int j2 = 0; j2 < 2; j2++)
#pragma unroll
                    for (int jj = 0; jj < 2; jj++) {
                        float* cc = acc[i][j2 * 2 + jj];
                        MMA_BF16(cc, ahf[i], bhf[j2][jj * 2], bhf[j2][jj * 2 + 1]);
                        MMA_BF16(cc, ahf[i], blf[j2][jj * 2], blf[j2][jj * 2 + 1]);
                        MMA_BF16(cc, alf[i], bhf[j2][jj * 2], bhf[j2][jj * 2 + 1]);
                    }
        }
        __syncthreads();
    }

    // ---- epilogue: direct stores (float2 per fragment half) ----
#pragma unroll
    for (int i = 0; i < 4; i++) {
#pragma unroll
        for (int j = 0; j < 4; j++) {
            int row = bm + m0 + i * 16 + (lane >> 2);
            int col = bn + n0 + j * 8 + (lane & 3) * 2;
            float bx = 0.0f, by = 0.0f;
            if (bias) { bx = bias[col]; by = bias[col + 1]; }
            float2 v0 = make_float2(acc[i][j][0] + bx, acc[i][j][1] + by);
            float2 v1 = make_float2(acc[i][j][2] + bx, acc[i][j][3] + by);
            *(float2*)(C + (size_t)row * N + col) = v0;
            *(float2*)(C + (size_t)(row + 8) * N + col) = v1;
        }
    }
}

// ---------------------------------------------------------------------------
// RoPE on Q (in place, token-major [b,s,h,d]).
// ---------------------------------------------------------------------------
__global__ __launch_bounds__(256) void rope_q_kernel(
    float* __restrict__ Q, const float* __restrict__ cosT,
    const float* __restrict__ sinT)
{
    const int row = blockIdx.x;
    const int s = row & (Ss - 1);
    float* qrow = Q + (size_t)row * HID;
    const float* cr = cosT + (size_t)s * HD;
    const float* sr = sinT + (size_t)s * HD;
    for (int p = threadIdx.x; p < NH * 64; p += blockDim.x) {
        const int h = p >> 6;
        const int d = p & 63;
        float* q = qrow + h * HD;
        float lo = q[d], hi = q[d + 64];
        q[d]      = lo * cr[d]      - hi * sr[d];
        q[d + 64] = hi * cr[d + 64] + lo * sr[d + 64];
    }
}

// ---------------------------------------------------------------------------
// RoPE on K + transpose K,V to [b, kv, s, d].
// ---------------------------------------------------------------------------
__global__ __launch_bounds__(256) void rope_kv_kernel(
    const float* __restrict__ KV, const float* __restrict__ cosT,
    const float* __restrict__ sinT, float* __restrict__ Kout,
    float* __restrict__ Vout)
{
    const int row = blockIdx.x;
    const int bq = row >> 11;
    const int s = row & (Ss - 1);
    const float* kvrow = KV + (size_t)row * KVW;
    const float* cr = cosT + (size_t)s * HD;
    const float* sr = sinT + (size_t)s * HD;
    for (int p = threadIdx.x; p < NKV * 64; p += blockDim.x) {
        const int kv = p >> 6;
        const int d = p & 63;
        const float* k = kvrow + kv * (2 * HD);
        const float* v = k + HD;
        float lo = k[d], hi = k[d + 64];
        size_t obase = ((size_t)(bq * NKV + kv) * Ss + s) * HD;
        Kout[obase + d]      = lo * cr[d]      - hi * sr[d];
        Kout[obase + d + 64] = hi * cr[d + 64] + lo * sr[d + 64];
        Vout[obase + d]      = v[d];
        Vout[obase + d + 64] = v[d + 64];
    }
}

// ---------------------------------------------------------------------------
// Flash attention, fp32 (R0 version, known good).
// ---------------------------------------------------------------------------
static constexpr int QS_STR = 129;
static constexpr int VS_STR = 132;
static constexpr int PS_STR = 65;
static constexpr int ATTN_SMEM_FLOATS = 64 * QS_STR * 2 + 64 * VS_STR + 64 * PS_STR;

__global__ __launch_bounds__(256) void flash_attn_kernel(
    const float* __restrict__ Q, const float* __restrict__ Kg,
    const float* __restrict__ Vg, float* __restrict__ Out)
{
    const int qt = blockIdx.x;
    const int h  = blockIdx.y;
    const int b  = blockIdx.z;
    const int kvh = h >> 2;

    extern __shared__ float sm[];
    float* Qs = sm;
    float* Ks = Qs + 64 * QS_STR;
    float* Vs = Ks + 64 * QS_STR;
    float* Ps = Vs + 64 * VS_STR;

    const int tid = threadIdx.x;
    const int tx = tid & 15;
    const int ty = tid >> 4;
    const float scale = 0.08838834764831845f;

    {
        const float* qbase = Q + ((size_t)(b * Ss + qt * 64)) * HID + h * HD;
        for (int idx = tid; idx < 64 * 32; idx += 256) {
            int r = idx >> 5;
            int c = (idx & 31) << 2;
            float4 v = *(const float4*)(qbase + (size_t)r * HID + c);
            float* dst = Qs + r * QS_STR + c;
            dst[0] = v.x * scale; dst[1] = v.y * scale;
            dst[2] = v.z * scale; dst[3] = v.w * scale;
        }
    }

    float mrow[4], lrow[4], o[4][8];
#pragma unroll
    for (int i = 0; i < 4; i++) {
        mrow[i] = -1e30f; lrow[i] = 0.0f;
#pragma unroll
        for (int j = 0; j < 8; j++) o[i][j] = 0.0f;
    }
    __syncthreads();

    const float* kbase0 = Kg + ((size_t)(b * NKV + kvh) * Ss) * HD;
    const float* vbase0 = Vg + ((size_t)(b * NKV + kvh) * Ss) * HD;

    for (int kt = 0; kt <= qt; kt++) {
        const float* kbase = kbase0 + (size_t)(kt * 64) * HD;
        const float* vbase = vbase0 + (size_t)(kt * 64) * HD;
        for (int idx = tid; idx < 64 * 32; idx += 256) {
            int r = idx >> 5;
            int c = (idx & 31) << 2;
            float4 kv4 = *(const float4*)(kbase + (size_t)r * HD + c);
            float* kd = Ks + r * QS_STR + c;
            kd[0] = kv4.x; kd[1] = kv4.y; kd[2] = kv4.z; kd[3] = kv4.w;
            float4 vv4 = *(const float4*)(vbase + (size_t)r * HD + c);
            *(float4*)(Vs + r * VS_STR + c) = vv4;
        }
        __syncthreads();

        float sacc[4][4];
#pragma unroll
        for (int i = 0; i < 4; i++)
#pragma unroll
            for (int j = 0; j < 4; j++) sacc[i][j] = 0.0f;

#pragma unroll 4
        for (int d = 0; d < HD; d++) {
            float ar[4], br[4];
#pragma unroll
            for (int i = 0; i < 4; i++) ar[i] = Qs[(ty * 4 + i) * QS_STR + d];
#pragma unroll
            for (int j = 0; j < 4; j++) br[j] = Ks[(tx * 4 + j) * QS_STR + d];
#pragma unroll
            for (int i = 0; i < 4; i++)
#pragma unroll
                for (int j = 0; j < 4; j++)
                    sacc[i][j] = fmaf(ar[i], br[j], sacc[i][j]);
        }

        if (kt == qt) {
#pragma unroll
            for (int i = 0; i < 4; i++)
#pragma unroll
                for (int j = 0; j < 4; j++)
                    if (tx * 4 + j > ty * 4 + i) sacc[i][j] = -1e30f;
        }

#pragma unroll
        for (int i = 0; i < 4; i++) {
            float mloc = fmaxf(fmaxf(sacc[i][0], sacc[i][1]),
                               fmaxf(sacc[i][2], sacc[i][3]));
#pragma unroll
            for (int off = 8; off >= 1; off >>= 1)
                mloc = fmaxf(mloc, __shfl_xor_sync(0xffffffffu, mloc, off));
            float mnew = fmaxf(mrow[i], mloc);
            float ls = 0.0f;
#pragma unroll
            for (int j = 0; j < 4; j++) {
                float p = __expf(sacc[i][j] - mnew);
                ls += p;
                Ps[(ty * 4 + i) * PS_STR + tx * 4 + j] = p;
            }
#pragma unroll
            for (int off = 8; off >= 1; off >>= 1)
                ls += __shfl_xor_sync(0xffffffffu, ls, off);
            float fac = __expf(mrow[i] - mnew);
            lrow[i] = lrow[i] * fac + ls;
            mrow[i] = mnew;
#pragma unroll
            for (int j = 0; j < 8; j++) o[i][j] *= fac;
        }
        __syncthreads();

#pragma unroll 2
        for (int kj = 0; kj < 64; kj++) {
            float pv[4];
#pragma unroll
            for (int i = 0; i < 4; i++) pv[i] = Ps[(ty * 4 + i) * PS_STR + kj];
            float4 v0 = *(const float4*)&Vs[kj * VS_STR + tx * 4];
            float4 v1 = *(const float4*)&Vs[kj * VS_STR + 64 + tx * 4];
            float vr[8] = {v0.x, v0.y, v0.z, v0.w, v1.x, v1.y, v1.z, v1.w};
#pragma unroll
            for (int i = 0; i < 4; i++)
#pragma unroll
                for (int j = 0; j < 8; j++)
                    o[i][j] = fmaf(pv[i], vr[j], o[i][j]);
        }
        __syncthreads();
    }

#pragma unroll
    for (int i = 0; i < 4; i++) {
        float inv = 1.0f / lrow[i];
        int qg = qt * 64 + ty * 4 + i;
        float* optr = Out + ((size_t)(b * Ss + qg)) * HID + h * HD;
        float4 o0 = make_float4(o[i][0] * inv, o[i][1] * inv, o[i][2] * inv, o[i][3] * inv);
        float4 o1 = make_float4(o[i][4] * inv, o[i][5] * inv, o[i][6] * inv, o[i][7] * inv);
        *(float4*)(optr + tx * 4) = o0;
        *(float4*)(optr + 64 + tx * 4) = o1;
    }
}

// ---------------------------------------------------------------------------
// Launch
// ---------------------------------------------------------------------------
extern "C" void kernel_launch(void* const* d_in, const int* in_sizes, int n_in,
                              void* d_out, int out_size)
{
    const float* hidden = (const float*)d_in[0];
    const float* cosT = (const float*)d_in[2];
    const float* sinT = (const float*)d_in[3];
    const float* Wq   = (const float*)d_in[4];
    const float* Wkv  = (const float*)d_in[5];
    const float* Wd   = (const float*)d_in[6];
    const float* bd   = (const float*)d_in[7];
    float* out = (float*)d_out;

    float *Qb, *KVb, *Kb, *Vb, *Ab;
    cudaGetSymbolAddress((void**)&Qb,  g_Q);
    cudaGetSymbolAddress((void**)&KVb, g_KV);
    cudaGetSymbolAddress((void**)&Kb,  g_K);
    cudaGetSymbolAddress((void**)&Vb,  g_V);
    cudaGetSymbolAddress((void**)&Ab,  g_attn);

    __nv_bfloat16 *hidH, *hidL, *wqH, *wqL, *wkvH, *wkvL, *wdH, *wdL, *atH, *atL;
    cudaGetSymbolAddress((void**)&hidH, g_hid_hi);
    cudaGetSymbolAddress((void**)&hidL, g_hid_lo);
    cudaGetSymbolAddress((void**)&wqH,  g_Wq_hi);
    cudaGetSymbolAddress((void**)&wqL,  g_Wq_lo);
    cudaGetSymbolAddress((void**)&wkvH, g_Wkv_hi);
    cudaGetSymbolAddress((void**)&wkvL, g_Wkv_lo);
    cudaGetSymbolAddress((void**)&wdH,  g_Wd_hi);
    cudaGetSymbolAddress((void**)&wdL,  g_Wd_lo);
    cudaGetSymbolAddress((void**)&atH,  g_at_hi);
    cudaGetSymbolAddress((void**)&atL,  g_at_lo);

    cudaFuncSetAttribute(gemm_mma_kernel,
                         cudaFuncAttributeMaxDynamicSharedMemorySize, GEMM_SMEM);
    size_t attn_smem = (size_t)ATTN_SMEM_FLOATS * sizeof(float);
    cudaFuncSetAttribute(flash_attn_kernel,
                         cudaFuncAttributeMaxDynamicSharedMemorySize, (int)attn_smem);

    // fp32 -> bf16 hi/lo splits
    const int n_hid = M_TOK * HID / 4;   // float4 count
    const int n_wkv = KVW * HID / 4;
    split_bf16_kernel<<<2048, 256>>>(hidden, hidH, hidL, n_hid);
    split_bf16_kernel<<<2048, 256>>>(Wq,  wqH,  wqL,  n_hid);
    split_bf16_kernel<<<2048, 256>>>(Wkv, wkvH, wkvL, n_wkv);
    split_bf16_kernel<<<2048, 256>>>(Wd,  wdH,  wdL,  n_hid);

    // Q and KV projections (tensor cores)
    gemm_mma_kernel<<<dim3(HID / 128, M_TOK / 128), 256, GEMM_SMEM>>>(
        hidH, hidL, wqH, wqL, nullptr, Qb, M_TOK, HID, HID);
    gemm_mma_kernel<<<dim3(KVW / 128, M_TOK / 128), 256, GEMM_SMEM>>>(
        hidH, hidL, wkvH, wkvL, nullptr, KVb, M_TOK, KVW, HID);

    // RoPE + K/V transpose
    rope_q_kernel<<<M_TOK, 256>>>(Qb, cosT, sinT);
    rope_kv_kernel<<<M_TOK, 256>>>(KVb, cosT, sinT, Kb, Vb);

    // Flash attention (fp32)
    flash_attn_kernel<<<dim3(Ss / 64, NH, Bb), 256, attn_smem>>>(Qb, Kb, Vb, Ab);

    // Output projection (tensor cores) + bias
    split_bf16_kernel<<<2048, 256>>>(Ab, atH, atL, n_hid);
    gemm_mma_kernel<<<dim3(HID / 128, M_TOK / 128), 256, GEMM_SMEM>>>(
        atH, atL, wdH, wdL, bd, out, M_TOK, HID, HID);
}

// round 5
// speedup vs baseline: 2.9382x; 1.5810x over previous
#include <cuda_runtime.h>
#include <cuda_bf16.h>
#include <math.h>
#include <stdint.h>

// ---------------------------------------------------------------------------
// TeleChat2 attention block, R4: projections AND flash attention on tensor
// cores via mma.sync bf16 hi/lo split (3-pass). fp32 only in accumulators.
// ---------------------------------------------------------------------------

static constexpr int Bb  = 2;
static constexpr int Ss  = 2048;
static constexpr int HID = 4096;
static constexpr int NH  = 32;
static constexpr int NKV = 8;
static constexpr int HD  = 128;
static constexpr int M_TOK = Bb * Ss;
static constexpr int KVW   = 2 * NKV * HD;

// fp32 scratch (projection outputs)
__device__ float g_Q [(size_t)M_TOK * HID];
__device__ float g_KV[(size_t)M_TOK * KVW];

// bf16 hi/lo splits
__device__ __nv_bfloat16 g_hid_hi[(size_t)M_TOK * HID];
__device__ __nv_bfloat16 g_hid_lo[(size_t)M_TOK * HID];
__device__ __nv_bfloat16 g_Wq_hi [(size_t)HID * HID];
__device__ __nv_bfloat16 g_Wq_lo [(size_t)HID * HID];
__device__ __nv_bfloat16 g_Wkv_hi[(size_t)KVW * HID];
__device__ __nv_bfloat16 g_Wkv_lo[(size_t)KVW * HID];
__device__ __nv_bfloat16 g_Wd_hi [(size_t)HID * HID];
__device__ __nv_bfloat16 g_Wd_lo [(size_t)HID * HID];
__device__ __nv_bfloat16 g_at_hi [(size_t)M_TOK * HID];
__device__ __nv_bfloat16 g_at_lo [(size_t)M_TOK * HID];
// roped Q (head-major [b,h,s,d], scaled by 1/sqrt(HD)), hi/lo
__device__ __nv_bfloat16 g_qh[(size_t)M_TOK * HID];
__device__ __nv_bfloat16 g_ql[(size_t)M_TOK * HID];
// roped K / V (head-major [b,kv,s,d]), hi/lo
__device__ __nv_bfloat16 g_kh[(size_t)Bb * NKV * Ss * HD];
__device__ __nv_bfloat16 g_kl[(size_t)Bb * NKV * Ss * HD];
__device__ __nv_bfloat16 g_vh[(size_t)Bb * NKV * Ss * HD];
__device__ __nv_bfloat16 g_vl[(size_t)Bb * NKV * Ss * HD];

// ---------------------------------------------------------------------------
// helpers
// ---------------------------------------------------------------------------
__device__ __forceinline__ uint32_t smem_u32(const void* p) {
    uint32_t a;
    asm("{ .reg .u64 t; cvta.to.shared.u64 t, %1; cvt.u32.u64 %0, t; }"
        : "=r"(a) : "l"(p));
    return a;
}

// GEMM swizzle (64B logical rows packed as 128B superrows)
__device__ __forceinline__ uint32_t sw_off(int row, int chunk) {
    int unit = ((row & 1) * 4 + chunk) ^ ((row >> 1) & 7);
    return (uint32_t)((row >> 1) * 128 + unit * 16);
}
// attention swizzle (256B rows, 16 chunks of 16B)
__device__ __forceinline__ uint32_t sw256(int row, int chunk) {
    return (uint32_t)(row * 256 + (((chunk ^ row) & 7) | (chunk & 8)) * 16);
}

#define LDSM_X4(r, addr) \
    asm volatile("ldmatrix.sync.aligned.m8n8.x4.shared.b16 {%0,%1,%2,%3}, [%4];" \
        : "=r"((r)[0]), "=r"((r)[1]), "=r"((r)[2]), "=r"((r)[3]) : "r"(addr))
#define LDSM_X4_T(r, addr) \
    asm volatile("ldmatrix.sync.aligned.m8n8.x4.trans.shared.b16 {%0,%1,%2,%3}, [%4];" \
        : "=r"((r)[0]), "=r"((r)[1]), "=r"((r)[2]), "=r"((r)[3]) : "r"(addr))

#define MMA_BF16(c, a, b0v, b1v) \
    asm volatile("mma.sync.aligned.m16n8k16.row.col.f32.bf16.bf16.f32 " \
        "{%0,%1,%2,%3}, {%4,%5,%6,%7}, {%8,%9}, {%0,%1,%2,%3};" \
        : "+f"((c)[0]), "+f"((c)[1]), "+f"((c)[2]), "+f"((c)[3]) \
        : "r"((a)[0]), "r"((a)[1]), "r"((a)[2]), "r"((a)[3]), "r"(b0v), "r"(b1v))

#define CP_ASYNC16(saddr, gptr) \
    asm volatile("cp.async.cg.shared.global [%0], [%1], 16;" \
        :: "r"(saddr), "l"(gptr) : "memory")
#define CP_COMMIT() asm volatile("cp.async.commit_group;" ::: "memory")
#define CP_WAIT(n)  asm volatile("cp.async.wait_group %0;" :: "n"(n) : "memory")

__device__ __forceinline__ void bsplit2(float x, float y,
                                        uint32_t& hi, uint32_t& lo) {
    __nv_bfloat16 hx = __float2bfloat16(x);
    __nv_bfloat16 hy = __float2bfloat16(y);
    __nv_bfloat16 lx = __float2bfloat16(x - __bfloat162float(hx));
    __nv_bfloat16 ly = __float2bfloat16(y - __bfloat162float(hy));
    __nv_bfloat162 h2(hx, hy), l2(lx, ly);
    hi = *(uint32_t*)&h2; lo = *(uint32_t*)&l2;
}

// ---------------------------------------------------------------------------
// fp32 -> (hi, lo) bf16 split
// ---------------------------------------------------------------------------
__global__ __launch_bounds__(256) void split_bf16_kernel(
    const float* __restrict__ in, __nv_bfloat16* __restrict__ hi,
    __nv_bfloat16* __restrict__ lo, int n4)
{
    int i = blockIdx.x * blockDim.x + threadIdx.x;
    int stride = gridDim.x * blockDim.x;
    const float4* in4 = (const float4*)in;
    __nv_bfloat162* h2 = (__nv_bfloat162*)hi;
    __nv_bfloat162* l2 = (__nv_bfloat162*)lo;
    for (; i < n4; i += stride) {
        float4 v = in4[i];
        __nv_bfloat16 hx = __float2bfloat16(v.x);
        __nv_bfloat16 hy = __float2bfloat16(v.y);
        __nv_bfloat16 hz = __float2bfloat16(v.z);
        __nv_bfloat16 hw = __float2bfloat16(v.w);
        __nv_bfloat16 lx = __float2bfloat16(v.x - __bfloat162float(hx));
        __nv_bfloat16 ly = __float2bfloat16(v.y - __bfloat162float(hy));
        __nv_bfloat16 lz = __float2bfloat16(v.z - __bfloat162float(hz));
        __nv_bfloat16 lw = __float2bfloat16(v.w - __bfloat162float(hw));
        h2[2 * i]     = __nv_bfloat162(hx, hy);
        h2[2 * i + 1] = __nv_bfloat162(hz, hw);
        l2[2 * i]     = __nv_bfloat162(lx, ly);
        l2[2 * i + 1] = __nv_bfloat162(lz, lw);
    }
}

// ---------------------------------------------------------------------------
// Tensor-core GEMM (R3, unchanged): C = A @ W^T (+bias), bf16 3-pass split.
// ---------------------------------------------------------------------------
static constexpr int GT = 8192;
static constexpr int GSTAGE = 4 * GT;
static constexpr int GEMM_SMEM = 2 * GSTAGE;

__global__ __launch_bounds__(256) void gemm_mma_kernel(
    const __nv_bfloat16* __restrict__ Ah, const __nv_bfloat16* __restrict__ Al,
    const __nv_bfloat16* __restrict__ Bh, const __nv_bfloat16* __restrict__ Bl,
    const float* __restrict__ bias, float* __restrict__ C,
    int M, int N, int K)
{
    extern __shared__ char smem[];
    const uint32_t sb = smem_u32(smem);
    const int tid  = threadIdx.x;
    const int wid  = tid >> 5;
    const int lane = tid & 31;
    const int bm = blockIdx.y * 128;
    const int bn = blockIdx.x * 128;
    const int m0 = (wid >> 2) * 64;
    const int n0 = (wid & 3) * 32;

    float acc[4][4][4];
#pragma unroll
    for (int i = 0; i < 4; i++)
#pragma unroll
        for (int j = 0; j < 4; j++)
#pragma unroll
            for (int r = 0; r < 4; r++) acc[i][j][r] = 0.0f;

    const int nchunk = K >> 5;

    auto load_stage = [&](int c, int stage) {
        const int k0 = c << 5;
        const uint32_t sbase = sb + stage * GSTAGE;
#pragma unroll
        for (int t = 0; t < 8; t++) {
            int op   = tid + t * 256;
            int tile = op >> 9;
            int idx  = op & 511;
            int row  = idx >> 2;
            int ch   = idx & 3;
            const __nv_bfloat16* src =
                (tile == 0) ? Ah : (tile == 1) ? Al : (tile == 2) ? Bh : Bl;
            int grow = ((tile < 2) ? bm : bn) + row;
            const void* g = src + (size_t)grow * K + k0 + ch * 8;
            uint32_t saddr = sbase + (uint32_t)tile * GT + sw_off(row, ch);
            CP_ASYNC16(saddr, g);
        }
        CP_COMMIT();
    };

    const int rA = ((lane >> 3) & 1) * 8 + (lane & 7);
    const int cA = (lane >> 4);
    const int rB = ((lane >> 4) & 1) * 8 + (lane & 7);
    const int cB = ((lane >> 3) & 1);

    load_stage(0, 0);

    for (int c = 0; c < nchunk; c++) {
        if (c + 1 < nchunk) { load_stage(c + 1, (c + 1) & 1); CP_WAIT(1); }
        else                { CP_WAIT(0); }
        __syncthreads();

        const uint32_t sbase = sb + (c & 1) * GSTAGE;
#pragma unroll
        for (int s = 0; s < 2; s++) {
            uint32_t ahf[4][4], alf[4][4], bhf[2][4], blf[2][4];
#pragma unroll
            for (int i = 0; i < 4; i++) {
                uint32_t off = sw_off(m0 + i * 16 + rA, 2 * s + cA);
                LDSM_X4(ahf[i], sbase + off);
                LDSM_X4(alf[i], sbase + GT + off);
            }
#pragma unroll
            for (int j2 = 0; j2 < 2; j2++) {
                uint32_t off = sw_off(n0 + j2 * 16 + rB, 2 * s + cB);
                LDSM_X4(bhf[j2], sbase + 2 * GT + off);
                LDSM_X4(blf[j2], sbase + 3 * GT + off);
            }
#pragma unroll
            for (int i = 0; i < 4; i++)
#pragma unroll
                for (int j2 = 0; j2 < 2; j2++)
#pragma unroll
                    for (int jj = 0; jj < 2; jj++) {
                        float* cc = acc[i][j2 * 2 + jj];
                        MMA_BF16(cc, ahf[i], bhf[j2][jj * 2], bhf[j2][jj * 2 + 1]);
                        MMA_BF16(cc, ahf[i], blf[j2][jj * 2], blf[j2][jj * 2 + 1]);
                        MMA_BF16(cc, alf[i], bhf[j2][jj * 2], bhf[j2][jj * 2 + 1]);
                    }
        }
        __syncthreads();
    }

#pragma unroll
    for (int i = 0; i < 4; i++) {
#pragma unroll
        for (int j = 0; j < 4; j++) {
            int row = bm + m0 + i * 16 + (lane >> 2);
            int col = bn + n0 + j * 8 + (lane & 3) * 2;
            float bx = 0.0f, by = 0.0f;
            if (bias) { bx = bias[col]; by = bias[col + 1]; }
            float2 v0 = make_float2(acc[i][j][0] + bx, acc[i][j][1] + by);
            float2 v1 = make_float2(acc[i][j][2] + bx, acc[i][j][3] + by);
            *(float2*)(C + (size_t)row * N + col) = v0;
            *(float2*)(C + (size_t)(row + 8) * N + col) = v1;
        }
    }
}

// ---------------------------------------------------------------------------
// RoPE on Q -> scaled bf16 hi/lo, head-major [b,h,s,d].
// ---------------------------------------------------------------------------
__global__ __launch_bounds__(256) void rope_q_split_kernel(
    const float* __restrict__ Q, const float* __restrict__ cosT,
    const float* __restrict__ sinT, __nv_bfloat16* __restrict__ qh,
    __nv_bfloat16* __restrict__ ql)
{
    const int row = blockIdx.x;
    const int b = row >> 11;
    const int s = row & (Ss - 1);
    const float scale = 0.08838834764831845f;  // 1/sqrt(128)
    const float* qrow = Q + (size_t)row * HID;
    const float* cr = cosT + (size_t)s * HD;
    const float* sr = sinT + (size_t)s * HD;
    for (int p = threadIdx.x; p < NH * 32; p += blockDim.x) {
        const int h = p >> 5;
        const int d = (p & 31) * 2;
        const float* q = qrow + h * HD;
        float lo0 = q[d],      lo1 = q[d + 1];
        float hi0 = q[d + 64], hi1 = q[d + 65];
        float e0 = (lo0 * cr[d]     - hi0 * sr[d])     * scale;
        float e1 = (lo1 * cr[d + 1] - hi1 * sr[d + 1]) * scale;
        float f0 = (hi0 * cr[d + 64] + lo0 * sr[d + 64]) * scale;
        float f1 = (hi1 * cr[d + 65] + lo1 * sr[d + 65]) * scale;
        size_t ob = ((size_t)(b * NH + h) * Ss + s) * HD;
        uint32_t ph, pl;
        bsplit2(e0, e1, ph, pl);
        *(uint32_t*)(qh + ob + d) = ph; *(uint32_t*)(ql + ob + d) = pl;
        bsplit2(f0, f1, ph, pl);
        *(uint32_t*)(qh + ob + d + 64) = ph; *(uint32_t*)(ql + ob + d + 64) = pl;
    }
}

// ---------------------------------------------------------------------------
// RoPE on K + V copy -> bf16 hi/lo, head-major [b,kv,s,d].
// ---------------------------------------------------------------------------
__global__ __launch_bounds__(256) void rope_kv_split_kernel(
    const float* __restrict__ KV, const float* __restrict__ cosT,
    const float* __restrict__ sinT,
    __nv_bfloat16* __restrict__ kh, __nv_bfloat16* __restrict__ kl,
    __nv_bfloat16* __restrict__ vh, __nv_bfloat16* __restrict__ vl)
{
    const int row = blockIdx.x;
    const int b = row >> 11;
    const int s = row & (Ss - 1);
    const float* kvrow = KV + (size_t)row * KVW;
    const float* cr = cosT + (size_t)s * HD;
    const float* sr = sinT + (size_t)s * HD;
    for (int p = threadIdx.x; p < NKV * 32; p += blockDim.x) {
        const int kv = p >> 5;
        const int d = (p & 31) * 2;
        const float* k = kvrow + kv * (2 * HD);
        const float* v = k + HD;
        float lo0 = k[d],      lo1 = k[d + 1];
        float hi0 = k[d + 64], hi1 = k[d + 65];
        float e0 = lo0 * cr[d]     - hi0 * sr[d];
        float e1 = lo1 * cr[d + 1] - hi1 * sr[d + 1];
        float f0 = hi0 * cr[d + 64] + lo0 * sr[d + 64];
        float f1 = hi1 * cr[d + 65] + lo1 * sr[d + 65];
        size_t ob = ((size_t)(b * NKV + kv) * Ss + s) * HD;
        uint32_t ph, pl;
        bsplit2(e0, e1, ph, pl);
        *(uint32_t*)(kh + ob + d) = ph; *(uint32_t*)(kl + ob + d) = pl;
        bsplit2(f0, f1, ph, pl);
        *(uint32_t*)(kh + ob + d + 64) = ph; *(uint32_t*)(kl + ob + d + 64) = pl;
        bsplit2(v[d], v[d + 1], ph, pl);
        *(uint32_t*)(vh + ob + d) = ph; *(uint32_t*)(vl + ob + d) = pl;
        bsplit2(v[d + 64], v[d + 65], ph, pl);
        *(uint32_t*)(vh + ob + d + 64) = ph; *(uint32_t*)(vl + ob + d + 64) = pl;
    }
}

// ---------------------------------------------------------------------------
// Flash attention on tensor cores. Grid (S/64, NH, B), 128 threads (4 warps).
// Tiles 64x64; smem: Qh Ql Kh Kl Vh Vl, each 64x128 bf16 (16KB), swizzled.
// Warp w owns q-rows [w*16, w*16+16). 3-pass hi/lo split on QK^T and PV.
// Output written directly as bf16 hi/lo split (token-major) for the O-proj.
// ---------------------------------------------------------------------------
static constexpr int AT = 64 * 256;           // 16KB tile
static constexpr int ATTN_SMEM = 6 * AT;      // 96KB

__global__ __launch_bounds__(128) void flash_attn_mma_kernel(
    const __nv_bfloat16* __restrict__ qh, const __nv_bfloat16* __restrict__ ql,
    const __nv_bfloat16* __restrict__ kh, const __nv_bfloat16* __restrict__ kl,
    const __nv_bfloat16* __restrict__ vh, const __nv_bfloat16* __restrict__ vl,
    __nv_bfloat16* __restrict__ atH, __nv_bfloat16* __restrict__ atL)
{
    extern __shared__ char smem[];
    const uint32_t sb = smem_u32(smem);
    const int qt = blockIdx.x;
    const int h  = blockIdx.y;
    const int b  = blockIdx.z;
    const int kvh = h >> 2;
    const int tid = threadIdx.x;
    const int wid = tid >> 5;
    const int lane = tid & 31;
    const int r0 = wid * 16;

    // lane-constant ldmatrix address components
    const int rA = (lane & 7) + ((lane >> 3) & 1) * 8;  // A and V(trans) rows
    const int cA = lane >> 4;                            // A and V chunk add
    const int rB = (lane & 7) + ((lane >> 4) & 1) * 8;  // K rows
    const int cB = (lane >> 3) & 1;                      // K chunk add

    // load Q tiles (hi, lo)
    const size_t qbase = ((size_t)(b * NH + h) * Ss + (size_t)qt * 64) * HD;
    for (int idx = tid; idx < 1024; idx += 128) {
        int r = idx >> 4, ch = idx & 15;
        uint32_t so = sw256(r, ch);
        const size_t g = qbase + (size_t)r * HD + ch * 8;
        CP_ASYNC16(sb + so, qh + g);
        CP_ASYNC16(sb + AT + so, ql + g);
    }
    CP_COMMIT();

    float oacc[16][4];
#pragma unroll
    for (int i = 0; i < 16; i++)
#pragma unroll
        for (int j = 0; j < 4; j++) oacc[i][j] = 0.0f;
    float mrow[2] = {-1e30f, -1e30f};
    float lrow[2] = {0.0f, 0.0f};

    const size_t kvbase = ((size_t)(b * NKV + kvh) * Ss) * HD;

    CP_WAIT(0);
    __syncthreads();

    for (int kt = 0; kt <= qt; kt++) {
        // load K/V tiles (hi, lo)
        const size_t kb = kvbase + (size_t)kt * 64 * HD;
        for (int idx = tid; idx < 1024; idx += 128) {
            int r = idx >> 4, ch = idx & 15;
            uint32_t so = sw256(r, ch);
            const size_t g = kb + (size_t)r * HD + ch * 8;
            CP_ASYNC16(sb + 2 * AT + so, kh + g);
            CP_ASYNC16(sb + 3 * AT + so, kl + g);
            CP_ASYNC16(sb + 4 * AT + so, vh + g);
            CP_ASYNC16(sb + 5 * AT + so, vl + g);
        }
        CP_COMMIT();
        CP_WAIT(0);
        __syncthreads();

        // ---- S = Q K^T (3-pass split) ----
        float sacc[8][4];
#pragma unroll
        for (int i = 0; i < 8; i++)
#pragma unroll
            for (int j = 0; j < 4; j++) sacc[i][j] = 0.0f;

#pragma unroll
        for (int kc = 0; kc < 8; kc++) {
            uint32_t ah[4], al[4];
            uint32_t offA = sw256(r0 + rA, 2 * kc + cA);
            LDSM_X4(ah, sb + offA);
            LDSM_X4(al, sb + AT + offA);
#pragma unroll
            for (int nbp = 0; nbp < 4; nbp++) {
                uint32_t bh[4], bl[4];
                uint32_t offB = sw256(nbp * 16 + rB, 2 * kc + cB);
                LDSM_X4(bh, sb + 2 * AT + offB);
                LDSM_X4(bl, sb + 3 * AT + offB);
#pragma unroll
                for (int jj = 0; jj < 2; jj++) {
                    float* cc = sacc[nbp * 2 + jj];
                    MMA_BF16(cc, ah, bh[jj * 2], bh[jj * 2 + 1]);
                    MMA_BF16(cc, ah, bl[jj * 2], bl[jj * 2 + 1]);
                    MMA_BF16(cc, al, bh[jj * 2], bh[jj * 2 + 1]);
                }
            }
        }

        // ---- causal mask on diagonal tile ----
        if (kt == qt) {
            const int rl = lane >> 2;
            const int c0 = (lane & 3) * 2;
#pragma unroll
            for (int nb = 0; nb < 8; nb++) {
#pragma unroll
                for (int j = 0; j < 4; j++) {
                    int col = nb * 8 + c0 + (j & 1);
                    int row = r0 + rl + (j >> 1) * 8;
                    if (col > row) sacc[nb][j] = -1e30f;
                }
            }
        }

        // ---- online softmax (2 rows per lane) ----
        float mx0 = -1e30f, mx1 = -1e30f;
#pragma unroll
        for (int nb = 0; nb < 8; nb++) {
            mx0 = fmaxf(mx0, fmaxf(sacc[nb][0], sacc[nb][1]));
            mx1 = fmaxf(mx1, fmaxf(sacc[nb][2], sacc[nb][3]));
        }
        mx0 = fmaxf(mx0, __shfl_xor_sync(0xffffffffu, mx0, 1));
        mx0 = fmaxf(mx0, __shfl_xor_sync(0xffffffffu, mx0, 2));
        mx1 = fmaxf(mx1, __shfl_xor_sync(0xffffffffu, mx1, 1));
        mx1 = fmaxf(mx1, __shfl_xor_sync(0xffffffffu, mx1, 2));
        float mn0 = fmaxf(mrow[0], mx0);
        float mn1 = fmaxf(mrow[1], mx1);
        float fac0 = __expf(mrow[0] - mn0);
        float fac1 = __expf(mrow[1] - mn1);
        mrow[0] = mn0; mrow[1] = mn1;
        lrow[0] *= fac0; lrow[1] *= fac1;
#pragma unroll
        for (int nb = 0; nb < 8; nb++) {
            float p0 = __expf(sacc[nb][0] - mn0);
            float p1 = __expf(sacc[nb][1] - mn0);
            float p2 = __expf(sacc[nb][2] - mn1);
            float p3 = __expf(sacc[nb][3] - mn1);
            lrow[0] += p0 + p1; lrow[1] += p2 + p3;
            sacc[nb][0] = p0; sacc[nb][1] = p1;
            sacc[nb][2] = p2; sacc[nb][3] = p3;
        }
#pragma unroll
        for (int db = 0; db < 16; db++) {
            oacc[db][0] *= fac0; oacc[db][1] *= fac0;
            oacc[db][2] *= fac1; oacc[db][3] *= fac1;
        }

        // ---- pack P into A-fragments (hi/lo split in registers) ----
        uint32_t aPh[4][4], aPl[4][4];
#pragma unroll
        for (int kc2 = 0; kc2 < 4; kc2++) {
            bsplit2(sacc[2 * kc2][0],     sacc[2 * kc2][1],     aPh[kc2][0], aPl[kc2][0]);
            bsplit2(sacc[2 * kc2][2],     sacc[2 * kc2][3],     aPh[kc2][1], aPl[kc2][1]);
            bsplit2(sacc[2 * kc2 + 1][0], sacc[2 * kc2 + 1][1], aPh[kc2][2], aPl[kc2][2]);
            bsplit2(sacc[2 * kc2 + 1][2], sacc[2 * kc2 + 1][3], aPh[kc2][3], aPl[kc2][3]);
        }

        // ---- O += P V (3-pass split), V via ldmatrix.trans ----
#pragma unroll
        for (int kc2 = 0; kc2 < 4; kc2++) {
#pragma unroll
            for (int dbp = 0; dbp < 8; dbp++) {
                uint32_t vhf[4], vlf[4];
                uint32_t offV = sw256(kc2 * 16 + rA, 2 * dbp + cA);
                LDSM_X4_T(vhf, sb + 4 * AT + offV);
                LDSM_X4_T(vlf, sb + 5 * AT + offV);
#pragma unroll
                for (int jj = 0; jj < 2; jj++) {
                    float* cc = oacc[dbp * 2 + jj];
                    MMA_BF16(cc, aPh[kc2], vhf[jj * 2], vhf[jj * 2 + 1]);
                    MMA_BF16(cc, aPh[kc2], vlf[jj * 2], vlf[jj * 2 + 1]);
                    MMA_BF16(cc, aPl[kc2], vhf[jj * 2], vhf[jj * 2 + 1]);
                }
            }
        }
        __syncthreads();  // protect smem tiles before next iteration's loads
    }

    // ---- finalize: normalize, split to bf16 hi/lo, store token-major ----
    lrow[0] += __shfl_xor_sync(0xffffffffu, lrow[0], 1);
    lrow[0] += __shfl_xor_sync(0xffffffffu, lrow[0], 2);
    lrow[1] += __shfl_xor_sync(0xffffffffu, lrow[1], 1);
    lrow[1] += __shfl_xor_sync(0xffffffffu, lrow[1], 2);
    const float inv0 = 1.0f / lrow[0];
    const float inv1 = 1.0f / lrow[1];
    const int rl = lane >> 2;
    const int c0 = (lane & 3) * 2;
    const size_t row0 = (size_t)(b * Ss + qt * 64 + r0 + rl) * HID + h * HD;
    const size_t row1 = row0 + (size_t)8 * HID;
#pragma unroll
    for (int db = 0; db < 16; db++) {
        const int col = db * 8 + c0;
        uint32_t ph, pl;
        bsplit2(oacc[db][0] * inv0, oacc[db][1] * inv0, ph, pl);
        *(uint32_t*)(atH + row0 + col) = ph;
        *(uint32_t*)(atL + row0 + col) = pl;
        bsplit2(oacc[db][2] * inv1, oacc[db][3] * inv1, ph, pl);
        *(uint32_t*)(atH + row1 + col) = ph;
        *(uint32_t*)(atL + row1 + col) = pl;
    }
}

// ---------------------------------------------------------------------------
// Launch
// ---------------------------------------------------------------------------
extern "C" void kernel_launch(void* const* d_in, const int* in_sizes, int n_in,
                              void* d_out, int out_size)
{
    const float* hidden = (const float*)d_in[0];
    const float* cosT = (const float*)d_in[2];
    const float* sinT = (const float*)d_in[3];
    const float* Wq   = (const float*)d_in[4];
    const float* Wkv  = (const float*)d_in[5];
    const float* Wd   = (const float*)d_in[6];
    const float* bd   = (const float*)d_in[7];
    float* out = (float*)d_out;

    float *Qb, *KVb;
    cudaGetSymbolAddress((void**)&Qb,  g_Q);
    cudaGetSymbolAddress((void**)&KVb, g_KV);

    __nv_bfloat16 *hidH, *hidL, *wqH, *wqL, *wkvH, *wkvL, *wdH, *wdL, *atH, *atL;
    __nv_bfloat16 *qh, *ql, *kh, *kl, *vh, *vl;
    cudaGetSymbolAddress((void**)&hidH, g_hid_hi);
    cudaGetSymbolAddress((void**)&hidL, g_hid_lo);
    cudaGetSymbolAddress((void**)&wqH,  g_Wq_hi);
    cudaGetSymbolAddress((void**)&wqL,  g_Wq_lo);
    cudaGetSymbolAddress((void**)&wkvH, g_Wkv_hi);
    cudaGetSymbolAddress((void**)&wkvL, g_Wkv_lo);
    cudaGetSymbolAddress((void**)&wdH,  g_Wd_hi);
    cudaGetSymbolAddress((void**)&wdL,  g_Wd_lo);
    cudaGetSymbolAddress((void**)&atH,  g_at_hi);
    cudaGetSymbolAddress((void**)&atL,  g_at_lo);
    cudaGetSymbolAddress((void**)&qh, g_qh);
    cudaGetSymbolAddress((void**)&ql, g_ql);
    cudaGetSymbolAddress((void**)&kh, g_kh);
    cudaGetSymbolAddress((void**)&kl, g_kl);
    cudaGetSymbolAddress((void**)&vh, g_vh);
    cudaGetSymbolAddress((void**)&vl, g_vl);

    cudaFuncSetAttribute(gemm_mma_kernel,
                         cudaFuncAttributeMaxDynamicSharedMemorySize, GEMM_SMEM);
    cudaFuncSetAttribute(flash_attn_mma_kernel,
                         cudaFuncAttributeMaxDynamicSharedMemorySize, ATTN_SMEM);

    // fp32 -> bf16 hi/lo splits of GEMM inputs
    const int n_hid = M_TOK * HID / 4;
    const int n_wkv = KVW * HID / 4;
    split_bf16_kernel<<<2048, 256>>>(hidden, hidH, hidL, n_hid);
    split_bf16_kernel<<<2048, 256>>>(Wq,  wqH,  wqL,  n_hid);
    split_bf16_kernel<<<2048, 256>>>(Wkv, wkvH, wkvL, n_wkv);
    split_bf16_kernel<<<2048, 256>>>(Wd,  wdH,  wdL,  n_hid);

    // Q and KV projections (tensor cores)
    gemm_mma_kernel<<<dim3(HID / 128, M_TOK / 128), 256, GEMM_SMEM>>>(
        hidH, hidL, wqH, wqL, nullptr, Qb, M_TOK, HID, HID);
    gemm_mma_kernel<<<dim3(KVW / 128, M_TOK / 128), 256, GEMM_SMEM>>>(
        hidH, hidL, wkvH, wkvL, nullptr, KVb, M_TOK, KVW, HID);

    // RoPE -> bf16 hi/lo head-major operands
    rope_q_split_kernel<<<M_TOK, 256>>>(Qb, cosT, sinT, qh, ql);
    rope_kv_split_kernel<<<M_TOK, 256>>>(KVb, cosT, sinT, kh, kl, vh, vl);

    // Flash attention (tensor cores), writes split output directly
    flash_attn_mma_kernel<<<dim3(Ss / 64, NH, Bb), 128, ATTN_SMEM>>>(
        qh, ql, kh, kl, vh, vl, atH, atL);

    // Output projection (tensor cores) + bias
    gemm_mma_kernel<<<dim3(HID / 128, M_TOK / 128), 256, GEMM_SMEM>>>(
        atH, atL, wdH, wdL, bd, out, M_TOK, HID, HID);
}

// round 6
// speedup vs baseline: 4.5454x; 1.5470x over previous
#include <cuda_runtime.h>
#include <cuda_bf16.h>
#include <cuda_fp16.h>
#include <math.h>
#include <stdint.h>

// ---------------------------------------------------------------------------
// TeleChat2 attention block, R5.
// Projection GEMMs: fp16 2-pass (activations single fp16, weights hi/lo fp16
//   pre-scaled x32, unscaled in epilogue).
// Flash attention: bf16 3-pass hi/lo (unchanged from R4), fp16 output.
// ---------------------------------------------------------------------------

static constexpr int Bb  = 2;
static constexpr int Ss  = 2048;
static constexpr int HID = 4096;
static constexpr int NH  = 32;
static constexpr int NKV = 8;
static constexpr int HD  = 128;
static constexpr int M_TOK = Bb * Ss;
static constexpr int KVW   = 2 * NKV * HD;

// fp32 scratch (projection outputs)
__device__ float g_Q [(size_t)M_TOK * HID];
__device__ float g_KV[(size_t)M_TOK * KVW];

// fp16 operands for projections
__device__ __half g_hidF [(size_t)M_TOK * HID];   // hidden, fp16
__device__ __half g_WqH  [(size_t)HID * HID];     // 32*Wq hi
__device__ __half g_WqL  [(size_t)HID * HID];     // 32*Wq lo
__device__ __half g_WkvH [(size_t)KVW * HID];
__device__ __half g_WkvL [(size_t)KVW * HID];
__device__ __half g_WdH  [(size_t)HID * HID];
__device__ __half g_WdL  [(size_t)HID * HID];
__device__ __half g_atF  [(size_t)M_TOK * HID];   // attention output, fp16

// bf16 hi/lo attention operands (head-major)
__device__ __nv_bfloat16 g_qh[(size_t)M_TOK * HID];
__device__ __nv_bfloat16 g_ql[(size_t)M_TOK * HID];
__device__ __nv_bfloat16 g_kh[(size_t)Bb * NKV * Ss * HD];
__device__ __nv_bfloat16 g_kl[(size_t)Bb * NKV * Ss * HD];
__device__ __nv_bfloat16 g_vh[(size_t)Bb * NKV * Ss * HD];
__device__ __nv_bfloat16 g_vl[(size_t)Bb * NKV * Ss * HD];

// ---------------------------------------------------------------------------
// helpers
// ---------------------------------------------------------------------------
__device__ __forceinline__ uint32_t smem_u32(const void* p) {
    uint32_t a;
    asm("{ .reg .u64 t; cvta.to.shared.u64 t, %1; cvt.u32.u64 %0, t; }"
        : "=r"(a) : "l"(p));
    return a;
}
__device__ __forceinline__ uint32_t sw_off(int row, int chunk) {
    int unit = ((row & 1) * 4 + chunk) ^ ((row >> 1) & 7);
    return (uint32_t)((row >> 1) * 128 + unit * 16);
}
__device__ __forceinline__ uint32_t sw256(int row, int chunk) {
    return (uint32_t)(row * 256 + (((chunk ^ row) & 7) | (chunk & 8)) * 16);
}

#define LDSM_X4(r, addr) \
    asm volatile("ldmatrix.sync.aligned.m8n8.x4.shared.b16 {%0,%1,%2,%3}, [%4];" \
        : "=r"((r)[0]), "=r"((r)[1]), "=r"((r)[2]), "=r"((r)[3]) : "r"(addr))
#define LDSM_X4_T(r, addr) \
    asm volatile("ldmatrix.sync.aligned.m8n8.x4.trans.shared.b16 {%0,%1,%2,%3}, [%4];" \
        : "=r"((r)[0]), "=r"((r)[1]), "=r"((r)[2]), "=r"((r)[3]) : "r"(addr))

#define MMA_BF16(c, a, b0v, b1v) \
    asm volatile("mma.sync.aligned.m16n8k16.row.col.f32.bf16.bf16.f32 " \
        "{%0,%1,%2,%3}, {%4,%5,%6,%7}, {%8,%9}, {%0,%1,%2,%3};" \
        : "+f"((c)[0]), "+f"((c)[1]), "+f"((c)[2]), "+f"((c)[3]) \
        : "r"((a)[0]), "r"((a)[1]), "r"((a)[2]), "r"((a)[3]), "r"(b0v), "r"(b1v))
#define MMA_FP16(c, a, b0v, b1v) \
    asm volatile("mma.sync.aligned.m16n8k16.row.col.f32.f16.f16.f32 " \
        "{%0,%1,%2,%3}, {%4,%5,%6,%7}, {%8,%9}, {%0,%1,%2,%3};" \
        : "+f"((c)[0]), "+f"((c)[1]), "+f"((c)[2]), "+f"((c)[3]) \
        : "r"((a)[0]), "r"((a)[1]), "r"((a)[2]), "r"((a)[3]), "r"(b0v), "r"(b1v))

#define CP_ASYNC16(saddr, gptr) \
    asm volatile("cp.async.cg.shared.global [%0], [%1], 16;" \
        :: "r"(saddr), "l"(gptr) : "memory")
#define CP_COMMIT() asm volatile("cp.async.commit_group;" ::: "memory")
#define CP_WAIT(n)  asm volatile("cp.async.wait_group %0;" :: "n"(n) : "memory")

__device__ __forceinline__ void bsplit2(float x, float y,
                                        uint32_t& hi, uint32_t& lo) {
    __nv_bfloat16 hx = __float2bfloat16(x);
    __nv_bfloat16 hy = __float2bfloat16(y);
    __nv_bfloat16 lx = __float2bfloat16(x - __bfloat162float(hx));
    __nv_bfloat16 ly = __float2bfloat16(y - __bfloat162float(hy));
    __nv_bfloat162 h2(hx, hy), l2(lx, ly);
    hi = *(uint32_t*)&h2; lo = *(uint32_t*)&l2;
}

// ---------------------------------------------------------------------------
// fp32 -> fp16 (activations)
// ---------------------------------------------------------------------------
__global__ __launch_bounds__(256) void conv_fp16_kernel(
    const float* __restrict__ in, __half* __restrict__ out, int n4)
{
    int i = blockIdx.x * blockDim.x + threadIdx.x;
    int stride = gridDim.x * blockDim.x;
    const float4* in4 = (const float4*)in;
    __half2* o2 = (__half2*)out;
    for (; i < n4; i += stride) {
        float4 v = in4[i];
        o2[2 * i]     = __floats2half2_rn(v.x, v.y);
        o2[2 * i + 1] = __floats2half2_rn(v.z, v.w);
    }
}

// ---------------------------------------------------------------------------
// fp32 weights -> fp16 (hi, lo) of 32*W
// ---------------------------------------------------------------------------
__global__ __launch_bounds__(256) void conv_wsplit_kernel(
    const float* __restrict__ in, __half* __restrict__ hi,
    __half* __restrict__ lo, int n4)
{
    int i = blockIdx.x * blockDim.x + threadIdx.x;
    int stride = gridDim.x * blockDim.x;
    const float4* in4 = (const float4*)in;
    __half2* h2 = (__half2*)hi;
    __half2* l2 = (__half2*)lo;
    for (; i < n4; i += stride) {
        float4 v = in4[i];
        float sx = v.x * 32.0f, sy = v.y * 32.0f;
        float sz = v.z * 32.0f, sw = v.w * 32.0f;
        __half hx = __float2half_rn(sx), hy = __float2half_rn(sy);
        __half hz = __float2half_rn(sz), hw = __float2half_rn(sw);
        __half lx = __float2half_rn(sx - __half2float(hx));
        __half ly = __float2half_rn(sy - __half2float(hy));
        __half lz = __float2half_rn(sz - __half2float(hz));
        __half lw = __float2half_rn(sw - __half2float(hw));
        h2[2 * i]     = __half2(hx, hy);
        h2[2 * i + 1] = __half2(hz, hw);
        l2[2 * i]     = __half2(lx, ly);
        l2[2 * i + 1] = __half2(lz, lw);
    }
}

// ---------------------------------------------------------------------------
// Tensor-core GEMM, fp16 2-pass: C[m,n] = (1/32) * sum_k A[m,k]*(Wh+Wl)[n,k]
// (+bias). CTA tile 128x128, BK=32, 256 threads = 8 warps (2m x 4n).
// smem per stage: A 8KB + Bh 8KB + Bl 8KB = 24KB, double-buffered.
// ---------------------------------------------------------------------------
static constexpr int GT = 8192;
static constexpr int GSTAGE = 3 * GT;            // 24 KB
static constexpr int GEMM_SMEM = 2 * GSTAGE;     // 48 KB

__global__ __launch_bounds__(256) void gemm_fp16x2_kernel(
    const __half* __restrict__ A, const __half* __restrict__ Bh,
    const __half* __restrict__ Bl, const float* __restrict__ bias,
    float* __restrict__ C, int M, int N, int K)
{
    extern __shared__ char smem[];
    const uint32_t sb = smem_u32(smem);
    const int tid  = threadIdx.x;
    const int wid  = tid >> 5;
    const int lane = tid & 31;
    const int bm = blockIdx.y * 128;
    const int bn = blockIdx.x * 128;
    const int m0 = (wid >> 2) * 64;
    const int n0 = (wid & 3) * 32;

    float acc[4][4][4];
#pragma unroll
    for (int i = 0; i < 4; i++)
#pragma unroll
        for (int j = 0; j < 4; j++)
#pragma unroll
            for (int r = 0; r < 4; r++) acc[i][j][r] = 0.0f;

    const int nchunk = K >> 5;

    auto load_stage = [&](int c, int stage) {
        const int k0 = c << 5;
        const uint32_t sbase = sb + stage * GSTAGE;
#pragma unroll
        for (int t = 0; t < 6; t++) {
            int op   = tid + t * 256;      // 0..1535
            int tile = op >> 9;            // 0 A, 1 Bh, 2 Bl
            int idx  = op & 511;
            int row  = idx >> 2;
            int ch   = idx & 3;
            const __half* src = (tile == 0) ? A : (tile == 1) ? Bh : Bl;
            int grow = ((tile == 0) ? bm : bn) + row;
            const void* g = src + (size_t)grow * K + k0 + ch * 8;
            uint32_t saddr = sbase + (uint32_t)tile * GT + sw_off(row, ch);
            CP_ASYNC16(saddr, g);
        }
        CP_COMMIT();
    };

    const int rA = ((lane >> 3) & 1) * 8 + (lane & 7);
    const int cA = (lane >> 4);
    const int rB = ((lane >> 4) & 1) * 8 + (lane & 7);
    const int cB = ((lane >> 3) & 1);

    load_stage(0, 0);

    for (int c = 0; c < nchunk; c++) {
        if (c + 1 < nchunk) { load_stage(c + 1, (c + 1) & 1); CP_WAIT(1); }
        else                { CP_WAIT(0); }
        __syncthreads();

        const uint32_t sbase = sb + (c & 1) * GSTAGE;
#pragma unroll
        for (int s = 0; s < 2; s++) {
            uint32_t af[4][4], bhf[2][4], blf[2][4];
#pragma unroll
            for (int i = 0; i < 4; i++) {
                uint32_t off = sw_off(m0 + i * 16 + rA, 2 * s + cA);
                LDSM_X4(af[i], sbase + off);
            }
#pragma unroll
            for (int j2 = 0; j2 < 2; j2++) {
                uint32_t off = sw_off(n0 + j2 * 16 + rB, 2 * s + cB);
                LDSM_X4(bhf[j2], sbase + GT + off);
                LDSM_X4(blf[j2], sbase + 2 * GT + off);
            }
#pragma unroll
            for (int i = 0; i < 4; i++)
#pragma unroll
                for (int j2 = 0; j2 < 2; j2++)
#pragma unroll
                    for (int jj = 0; jj < 2; jj++) {
                        float* cc = acc[i][j2 * 2 + jj];
                        MMA_FP16(cc, af[i], bhf[j2][jj * 2], bhf[j2][jj * 2 + 1]);
                        MMA_FP16(cc, af[i], blf[j2][jj * 2], blf[j2][jj * 2 + 1]);
                    }
        }
        __syncthreads();
    }

    const float inv32 = 0.03125f;
#pragma unroll
    for (int i = 0; i < 4; i++) {
#pragma unroll
        for (int j = 0; j < 4; j++) {
            int row = bm + m0 + i * 16 + (lane >> 2);
            int col = bn + n0 + j * 8 + (lane & 3) * 2;
            float bx = 0.0f, by = 0.0f;
            if (bias) { bx = bias[col]; by = bias[col + 1]; }
            float2 v0 = make_float2(acc[i][j][0] * inv32 + bx,
                                    acc[i][j][1] * inv32 + by);
            float2 v1 = make_float2(acc[i][j][2] * inv32 + bx,
                                    acc[i][j][3] * inv32 + by);
            *(float2*)(C + (size_t)row * N + col) = v0;
            *(float2*)(C + (size_t)(row + 8) * N + col) = v1;
        }
    }
}

// ---------------------------------------------------------------------------
// RoPE on Q -> scaled bf16 hi/lo, head-major [b,h,s,d].
// ---------------------------------------------------------------------------
__global__ __launch_bounds__(256) void rope_q_split_kernel(
    const float* __restrict__ Q, const float* __restrict__ cosT,
    const float* __restrict__ sinT, __nv_bfloat16* __restrict__ qh,
    __nv_bfloat16* __restrict__ ql)
{
    const int row = blockIdx.x;
    const int b = row >> 11;
    const int s = row & (Ss - 1);
    const float scale = 0.08838834764831845f;
    const float* qrow = Q + (size_t)row * HID;
    const float* cr = cosT + (size_t)s * HD;
    const float* sr = sinT + (size_t)s * HD;
    for (int p = threadIdx.x; p < NH * 32; p += blockDim.x) {
        const int h = p >> 5;
        const int d = (p & 31) * 2;
        const float* q = qrow + h * HD;
        float lo0 = q[d],      lo1 = q[d + 1];
        float hi0 = q[d + 64], hi1 = q[d + 65];
        float e0 = (lo0 * cr[d]     - hi0 * sr[d])     * scale;
        float e1 = (lo1 * cr[d + 1] - hi1 * sr[d + 1]) * scale;
        float f0 = (hi0 * cr[d + 64] + lo0 * sr[d + 64]) * scale;
        float f1 = (hi1 * cr[d + 65] + lo1 * sr[d + 65]) * scale;
        size_t ob = ((size_t)(b * NH + h) * Ss + s) * HD;
        uint32_t ph, pl;
        bsplit2(e0, e1, ph, pl);
        *(uint32_t*)(qh + ob + d) = ph; *(uint32_t*)(ql + ob + d) = pl;
        bsplit2(f0, f1, ph, pl);
        *(uint32_t*)(qh + ob + d + 64) = ph; *(uint32_t*)(ql + ob + d + 64) = pl;
    }
}

// ---------------------------------------------------------------------------
// RoPE on K + V copy -> bf16 hi/lo, head-major [b,kv,s,d].
// ---------------------------------------------------------------------------
__global__ __launch_bounds__(256) void rope_kv_split_kernel(
    const float* __restrict__ KV, const float* __restrict__ cosT,
    const float* __restrict__ sinT,
    __nv_bfloat16* __restrict__ kh, __nv_bfloat16* __restrict__ kl,
    __nv_bfloat16* __restrict__ vh, __nv_bfloat16* __restrict__ vl)
{
    const int row = blockIdx.x;
    const int b = row >> 11;
    const int s = row & (Ss - 1);
    const float* kvrow = KV + (size_t)row * KVW;
    const float* cr = cosT + (size_t)s * HD;
    const float* sr = sinT + (size_t)s * HD;
    for (int p = threadIdx.x; p < NKV * 32; p += blockDim.x) {
        const int kv = p >> 5;
        const int d = (p & 31) * 2;
        const float* k = kvrow + kv * (2 * HD);
        const float* v = k + HD;
        float lo0 = k[d],      lo1 = k[d + 1];
        float hi0 = k[d + 64], hi1 = k[d + 65];
        float e0 = lo0 * cr[d]     - hi0 * sr[d];
        float e1 = lo1 * cr[d + 1] - hi1 * sr[d + 1];
        float f0 = hi0 * cr[d + 64] + lo0 * sr[d + 64];
        float f1 = hi1 * cr[d + 65] + lo1 * sr[d + 65];
        size_t ob = ((size_t)(b * NKV + kv) * Ss + s) * HD;
        uint32_t ph, pl;
        bsplit2(e0, e1, ph, pl);
        *(uint32_t*)(kh + ob + d) = ph; *(uint32_t*)(kl + ob + d) = pl;
        bsplit2(f0, f1, ph, pl);
        *(uint32_t*)(kh + ob + d + 64) = ph; *(uint32_t*)(kl + ob + d + 64) = pl;
        bsplit2(v[d], v[d + 1], ph, pl);
        *(uint32_t*)(vh + ob + d) = ph; *(uint32_t*)(vl + ob + d) = pl;
        bsplit2(v[d + 64], v[d + 65], ph, pl);
        *(uint32_t*)(vh + ob + d + 64) = ph; *(uint32_t*)(vl + ob + d + 64) = pl;
    }
}

// ---------------------------------------------------------------------------
// Flash attention on tensor cores (bf16 3-pass), fp16 output.
// Grid (S/64, NH, B), 128 threads (4 warps); tiles 64x64.
// ---------------------------------------------------------------------------
static constexpr int AT = 64 * 256;
static constexpr int ATTN_SMEM = 6 * AT;   // 96 KB

__global__ __launch_bounds__(128) void flash_attn_mma_kernel(
    const __nv_bfloat16* __restrict__ qh, const __nv_bfloat16* __restrict__ ql,
    const __nv_bfloat16* __restrict__ kh, const __nv_bfloat16* __restrict__ kl,
    const __nv_bfloat16* __restrict__ vh, const __nv_bfloat16* __restrict__ vl,
    __half* __restrict__ atF)
{
    extern __shared__ char smem[];
    const uint32_t sb = smem_u32(smem);
    const int qt = blockIdx.x;
    const int h  = blockIdx.y;
    const int b  = blockIdx.z;
    const int kvh = h >> 2;
    const int tid = threadIdx.x;
    const int wid = tid >> 5;
    const int lane = tid & 31;
    const int r0 = wid * 16;

    const int rA = (lane & 7) + ((lane >> 3) & 1) * 8;
    const int cA = lane >> 4;
    const int rB = (lane & 7) + ((lane >> 4) & 1) * 8;
    const int cB = (lane >> 3) & 1;

    const size_t qbase = ((size_t)(b * NH + h) * Ss + (size_t)qt * 64) * HD;
    for (int idx = tid; idx < 1024; idx += 128) {
        int r = idx >> 4, ch = idx & 15;
        uint32_t so = sw256(r, ch);
        const size_t g = qbase + (size_t)r * HD + ch * 8;
        CP_ASYNC16(sb + so, qh + g);
        CP_ASYNC16(sb + AT + so, ql + g);
    }
    CP_COMMIT();

    float oacc[16][4];
#pragma unroll
    for (int i = 0; i < 16; i++)
#pragma unroll
        for (int j = 0; j < 4; j++) oacc[i][j] = 0.0f;
    float mrow[2] = {-1e30f, -1e30f};
    float lrow[2] = {0.0f, 0.0f};

    const size_t kvbase = ((size_t)(b * NKV + kvh) * Ss) * HD;

    CP_WAIT(0);
    __syncthreads();

    for (int kt = 0; kt <= qt; kt++) {
        const size_t kb = kvbase + (size_t)kt * 64 * HD;
        for (int idx = tid; idx < 1024; idx += 128) {
            int r = idx >> 4, ch = idx & 15;
            uint32_t so = sw256(r, ch);
            const size_t g = kb + (size_t)r * HD + ch * 8;
            CP_ASYNC16(sb + 2 * AT + so, kh + g);
            CP_ASYNC16(sb + 3 * AT + so, kl + g);
            CP_ASYNC16(sb + 4 * AT + so, vh + g);
            CP_ASYNC16(sb + 5 * AT + so, vl + g);
        }
        CP_COMMIT();
        CP_WAIT(0);
        __syncthreads();

        float sacc[8][4];
#pragma unroll
        for (int i = 0; i < 8; i++)
#pragma unroll
            for (int j = 0; j < 4; j++) sacc[i][j] = 0.0f;

#pragma unroll
        for (int kc = 0; kc < 8; kc++) {
            uint32_t ah[4], al[4];
            uint32_t offA = sw256(r0 + rA, 2 * kc + cA);
            LDSM_X4(ah, sb + offA);
            LDSM_X4(al, sb + AT + offA);
#pragma unroll
            for (int nbp = 0; nbp < 4; nbp++) {
                uint32_t bh[4], bl[4];
                uint32_t offB = sw256(nbp * 16 + rB, 2 * kc + cB);
                LDSM_X4(bh, sb + 2 * AT + offB);
                LDSM_X4(bl, sb + 3 * AT + offB);
#pragma unroll
                for (int jj = 0; jj < 2; jj++) {
                    float* cc = sacc[nbp * 2 + jj];
                    MMA_BF16(cc, ah, bh[jj * 2], bh[jj * 2 + 1]);
                    MMA_BF16(cc, ah, bl[jj * 2], bl[jj * 2 + 1]);
                    MMA_BF16(cc, al, bh[jj * 2], bh[jj * 2 + 1]);
                }
            }
        }

        if (kt == qt) {
            const int rl = lane >> 2;
            const int c0 = (lane & 3) * 2;
#pragma unroll
            for (int nb = 0; nb < 8; nb++) {
#pragma unroll
                for (int j = 0; j < 4; j++) {
                    int col = nb * 8 + c0 + (j & 1);
                    int row = r0 + rl + (j >> 1) * 8;
                    if (col > row) sacc[nb][j] = -1e30f;
                }
            }
        }

        float mx0 = -1e30f, mx1 = -1e30f;
#pragma unroll
        for (int nb = 0; nb < 8; nb++) {
            mx0 = fmaxf(mx0, fmaxf(sacc[nb][0], sacc[nb][1]));
            mx1 = fmaxf(mx1, fmaxf(sacc[nb][2], sacc[nb][3]));
        }
        mx0 = fmaxf(mx0, __shfl_xor_sync(0xffffffffu, mx0, 1));
        mx0 = fmaxf(mx0, __shfl_xor_sync(0xffffffffu, mx0, 2));
        mx1 = fmaxf(mx1, __shfl_xor_sync(0xffffffffu, mx1, 1));
        mx1 = fmaxf(mx1, __shfl_xor_sync(0xffffffffu, mx1, 2));
        float mn0 = fmaxf(mrow[0], mx0);
        float mn1 = fmaxf(mrow[1], mx1);
        float fac0 = __expf(mrow[0] - mn0);
        float fac1 = __expf(mrow[1] - mn1);
        mrow[0] = mn0; mrow[1] = mn1;
        lrow[0] *= fac0; lrow[1] *= fac1;
#pragma unroll
        for (int nb = 0; nb < 8; nb++) {
            float p0 = __expf(sacc[nb][0] - mn0);
            float p1 = __expf(sacc[nb][1] - mn0);
            float p2 = __expf(sacc[nb][2] - mn1);
            float p3 = __expf(sacc[nb][3] - mn1);
            lrow[0] += p0 + p1; lrow[1] += p2 + p3;
            sacc[nb][0] = p0; sacc[nb][1] = p1;
            sacc[nb][2] = p2; sacc[nb][3] = p3;
        }
#pragma unroll
        for (int db = 0; db < 16; db++) {
            oacc[db][0] *= fac0; oacc[db][1] *= fac0;
            oacc[db][2] *= fac1; oacc[db][3] *= fac1;
        }

        uint32_t aPh[4][4], aPl[4][4];
#pragma unroll
        for (int kc2 = 0; kc2 < 4; kc2++) {
            bsplit2(sacc[2 * kc2][0],     sacc[2 * kc2][1],     aPh[kc2][0], aPl[kc2][0]);
            bsplit2(sacc[2 * kc2][2],     sacc[2 * kc2][3],     aPh[kc2][1], aPl[kc2][1]);
            bsplit2(sacc[2 * kc2 + 1][0], sacc[2 * kc2 + 1][1], aPh[kc2][2], aPl[kc2][2]);
            bsplit2(sacc[2 * kc2 + 1][2], sacc[2 * kc2 + 1][3], aPh[kc2][3], aPl[kc2][3]);
        }

#pragma unroll
        for (int kc2 = 0; kc2 < 4; kc2++) {
#pragma unroll
            for (int dbp = 0; dbp < 8; dbp++) {
                uint32_t vhf[4], vlf[4];
                uint32_t offV = sw256(kc2 * 16 + rA, 2 * dbp + cA);
                LDSM_X4_T(vhf, sb + 4 * AT + offV);
                LDSM_X4_T(vlf, sb + 5 * AT + offV);
#pragma unroll
                for (int jj = 0; jj < 2; jj++) {
                    float* cc = oacc[dbp * 2 + jj];
                    MMA_BF16(cc, aPh[kc2], vhf[jj * 2], vhf[jj * 2 + 1]);
                    MMA_BF16(cc, aPh[kc2], vlf[jj * 2], vlf[jj * 2 + 1]);
                    MMA_BF16(cc, aPl[kc2], vhf[jj * 2], vhf[jj * 2 + 1]);
                }
            }
        }
        __syncthreads();
    }

    lrow[0] += __shfl_xor_sync(0xffffffffu, lrow[0], 1);
    lrow[0] += __shfl_xor_sync(0xffffffffu, lrow[0], 2);
    lrow[1] += __shfl_xor_sync(0xffffffffu, lrow[1], 1);
    lrow[1] += __shfl_xor_sync(0xffffffffu, lrow[1], 2);
    const float inv0 = 1.0f / lrow[0];
    const float inv1 = 1.0f / lrow[1];
    const int rl = lane >> 2;
    const int c0 = (lane & 3) * 2;
    const size_t row0 = (size_t)(b * Ss + qt * 64 + r0 + rl) * HID + h * HD;
    const size_t row1 = row0 + (size_t)8 * HID;
#pragma unroll
    for (int db = 0; db < 16; db++) {
        const int col = db * 8 + c0;
        __half2 a = __floats2half2_rn(oacc[db][0] * inv0, oacc[db][1] * inv0);
        __half2 c = __floats2half2_rn(oacc[db][2] * inv1, oacc[db][3] * inv1);
        *(__half2*)(atF + row0 + col) = a;
        *(__half2*)(atF + row1 + col) = c;
    }
}

// ---------------------------------------------------------------------------
// Launch
// ---------------------------------------------------------------------------
extern "C" void kernel_launch(void* const* d_in, const int* in_sizes, int n_in,
                              void* d_out, int out_size)
{
    const float* hidden = (const float*)d_in[0];
    const float* cosT = (const float*)d_in[2];
    const float* sinT = (const float*)d_in[3];
    const float* Wq   = (const float*)d_in[4];
    const float* Wkv  = (const float*)d_in[5];
    const float* Wd   = (const float*)d_in[6];
    const float* bd   = (const float*)d_in[7];
    float* out = (float*)d_out;

    float *Qb, *KVb;
    cudaGetSymbolAddress((void**)&Qb,  g_Q);
    cudaGetSymbolAddress((void**)&KVb, g_KV);

    __half *hidF, *wqH, *wqL, *wkvH, *wkvL, *wdH, *wdL, *atF;
    cudaGetSymbolAddress((void**)&hidF, g_hidF);
    cudaGetSymbolAddress((void**)&wqH,  g_WqH);
    cudaGetSymbolAddress((void**)&wqL,  g_WqL);
    cudaGetSymbolAddress((void**)&wkvH, g_WkvH);
    cudaGetSymbolAddress((void**)&wkvL, g_WkvL);
    cudaGetSymbolAddress((void**)&wdH,  g_WdH);
    cudaGetSymbolAddress((void**)&wdL,  g_WdL);
    cudaGetSymbolAddress((void**)&atF,  g_atF);

    __nv_bfloat16 *qh, *ql, *kh, *kl, *vh, *vl;
    cudaGetSymbolAddress((void**)&qh, g_qh);
    cudaGetSymbolAddress((void**)&ql, g_ql);
    cudaGetSymbolAddress((void**)&kh, g_kh);
    cudaGetSymbolAddress((void**)&kl, g_kl);
    cudaGetSymbolAddress((void**)&vh, g_vh);
    cudaGetSymbolAddress((void**)&vl, g_vl);

    cudaFuncSetAttribute(gemm_fp16x2_kernel,
                         cudaFuncAttributeMaxDynamicSharedMemorySize, GEMM_SMEM);
    cudaFuncSetAttribute(flash_attn_mma_kernel,
                         cudaFuncAttributeMaxDynamicSharedMemorySize, ATTN_SMEM);

    // conversions
    const int n_hid = M_TOK * HID / 4;
    const int n_wkv = KVW * HID / 4;
    conv_fp16_kernel  <<<2048, 256>>>(hidden, hidF, n_hid);
    conv_wsplit_kernel<<<2048, 256>>>(Wq,  wqH,  wqL,  n_hid);
    conv_wsplit_kernel<<<2048, 256>>>(Wkv, wkvH, wkvL, n_wkv);
    conv_wsplit_kernel<<<2048, 256>>>(Wd,  wdH,  wdL,  n_hid);

    // Q and KV projections (fp16 2-pass)
    gemm_fp16x2_kernel<<<dim3(HID / 128, M_TOK / 128), 256, GEMM_SMEM>>>(
        hidF, wqH, wqL, nullptr, Qb, M_TOK, HID, HID);
    gemm_fp16x2_kernel<<<dim3(KVW / 128, M_TOK / 128), 256, GEMM_SMEM>>>(
        hidF, wkvH, wkvL, nullptr, KVb, M_TOK, KVW, HID);

    // RoPE -> bf16 hi/lo head-major operands
    rope_q_split_kernel<<<M_TOK, 256>>>(Qb, cosT, sinT, qh, ql);
    rope_kv_split_kernel<<<M_TOK, 256>>>(KVb, cosT, sinT, kh, kl, vh, vl);

    // Flash attention (bf16 3-pass), fp16 output
    flash_attn_mma_kernel<<<dim3(Ss / 64, NH, Bb), 128, ATTN_SMEM>>>(
        qh, ql, kh, kl, vh, vl, atF);

    // Output projection (fp16 2-pass) + bias
    gemm_fp16x2_kernel<<<dim3(HID / 128, M_TOK / 128), 256, GEMM_SMEM>>>(
        atF, wdH, wdL, bd, out, M_TOK, HID, HID);
}

// round 7
// speedup vs baseline: 4.8969x; 1.0773x over previous
#include <cuda_runtime.h>
#include <cuda_bf16.h>
#include <cuda_fp16.h>
#include <math.h>
#include <stdint.h>

// ---------------------------------------------------------------------------
// TeleChat2 attention block, R6.
// Projection GEMMs: fp16 2-pass (activations fp16 once, weights hi/lo x32).
// Flash attention: fp16 2-pass QK^T (Q hi/lo, K once) + 2-pass PV
//   (P hi/lo x512, V once). All accumulation fp32.
// ---------------------------------------------------------------------------

static constexpr int Bb  = 2;
static constexpr int Ss  = 2048;
static constexpr int HID = 4096;
static constexpr int NH  = 32;
static constexpr int NKV = 8;
static constexpr int HD  = 128;
static constexpr int M_TOK = Bb * Ss;
static constexpr int KVW   = 2 * NKV * HD;

// fp32 scratch (projection outputs)
__device__ float g_Q [(size_t)M_TOK * HID];
__device__ float g_KV[(size_t)M_TOK * KVW];

// fp16 operands for projections
__device__ __half g_hidF [(size_t)M_TOK * HID];
__device__ __half g_WqH  [(size_t)HID * HID];
__device__ __half g_WqL  [(size_t)HID * HID];
__device__ __half g_WkvH [(size_t)KVW * HID];
__device__ __half g_WkvL [(size_t)KVW * HID];
__device__ __half g_WdH  [(size_t)HID * HID];
__device__ __half g_WdL  [(size_t)HID * HID];
__device__ __half g_atF  [(size_t)M_TOK * HID];

// fp16 attention operands (head-major)
__device__ __half g_qh[(size_t)M_TOK * HID];        // roped Q hi (unscaled)
__device__ __half g_ql[(size_t)M_TOK * HID];        // roped Q lo
__device__ __half g_kF[(size_t)Bb * NKV * Ss * HD]; // roped K
__device__ __half g_vF[(size_t)Bb * NKV * Ss * HD]; // V

// ---------------------------------------------------------------------------
// helpers
// ---------------------------------------------------------------------------
__device__ __forceinline__ uint32_t smem_u32(const void* p) {
    uint32_t a;
    asm("{ .reg .u64 t; cvta.to.shared.u64 t, %1; cvt.u32.u64 %0, t; }"
        : "=r"(a) : "l"(p));
    return a;
}
__device__ __forceinline__ uint32_t sw_off(int row, int chunk) {
    int unit = ((row & 1) * 4 + chunk) ^ ((row >> 1) & 7);
    return (uint32_t)((row >> 1) * 128 + unit * 16);
}
__device__ __forceinline__ uint32_t sw256(int row, int chunk) {
    return (uint32_t)(row * 256 + (((chunk ^ row) & 7) | (chunk & 8)) * 16);
}

#define LDSM_X4(r, addr) \
    asm volatile("ldmatrix.sync.aligned.m8n8.x4.shared.b16 {%0,%1,%2,%3}, [%4];" \
        : "=r"((r)[0]), "=r"((r)[1]), "=r"((r)[2]), "=r"((r)[3]) : "r"(addr))
#define LDSM_X4_T(r, addr) \
    asm volatile("ldmatrix.sync.aligned.m8n8.x4.trans.shared.b16 {%0,%1,%2,%3}, [%4];" \
        : "=r"((r)[0]), "=r"((r)[1]), "=r"((r)[2]), "=r"((r)[3]) : "r"(addr))

#define MMA_FP16(c, a, b0v, b1v) \
    asm volatile("mma.sync.aligned.m16n8k16.row.col.f32.f16.f16.f32 " \
        "{%0,%1,%2,%3}, {%4,%5,%6,%7}, {%8,%9}, {%0,%1,%2,%3};" \
        : "+f"((c)[0]), "+f"((c)[1]), "+f"((c)[2]), "+f"((c)[3]) \
        : "r"((a)[0]), "r"((a)[1]), "r"((a)[2]), "r"((a)[3]), "r"(b0v), "r"(b1v))

#define CP_ASYNC16(saddr, gptr) \
    asm volatile("cp.async.cg.shared.global [%0], [%1], 16;" \
        :: "r"(saddr), "l"(gptr) : "memory")
#define CP_COMMIT() asm volatile("cp.async.commit_group;" ::: "memory")
#define CP_WAIT(n)  asm volatile("cp.async.wait_group %0;" :: "n"(n) : "memory")

__device__ __forceinline__ void hsplit2(float x, float y,
                                        uint32_t& hi, uint32_t& lo) {
    __half hx = __float2half_rn(x);
    __half hy = __float2half_rn(y);
    __half lx = __float2half_rn(x - __half2float(hx));
    __half ly = __float2half_rn(y - __half2float(hy));
    __half2 h2(hx, hy), l2(lx, ly);
    hi = *(uint32_t*)&h2; lo = *(uint32_t*)&l2;
}

// ---------------------------------------------------------------------------
// fp32 -> fp16 (activations)
// ---------------------------------------------------------------------------
__global__ __launch_bounds__(256) void conv_fp16_kernel(
    const float* __restrict__ in, __half* __restrict__ out, int n4)
{
    int i = blockIdx.x * blockDim.x + threadIdx.x;
    int stride = gridDim.x * blockDim.x;
    const float4* in4 = (const float4*)in;
    __half2* o2 = (__half2*)out;
    for (; i < n4; i += stride) {
        float4 v = in4[i];
        o2[2 * i]     = __floats2half2_rn(v.x, v.y);
        o2[2 * i + 1] = __floats2half2_rn(v.z, v.w);
    }
}

// ---------------------------------------------------------------------------
// fp32 weights -> fp16 (hi, lo) of 32*W
// ---------------------------------------------------------------------------
__global__ __launch_bounds__(256) void conv_wsplit_kernel(
    const float* __restrict__ in, __half* __restrict__ hi,
    __half* __restrict__ lo, int n4)
{
    int i = blockIdx.x * blockDim.x + threadIdx.x;
    int stride = gridDim.x * blockDim.x;
    const float4* in4 = (const float4*)in;
    __half2* h2 = (__half2*)hi;
    __half2* l2 = (__half2*)lo;
    for (; i < n4; i += stride) {
        float4 v = in4[i];
        uint32_t ph, pl;
        hsplit2(v.x * 32.0f, v.y * 32.0f, ph, pl);
        h2[2 * i] = *(__half2*)&ph; l2[2 * i] = *(__half2*)&pl;
        hsplit2(v.z * 32.0f, v.w * 32.0f, ph, pl);
        h2[2 * i + 1] = *(__half2*)&ph; l2[2 * i + 1] = *(__half2*)&pl;
    }
}

// ---------------------------------------------------------------------------
// Tensor-core GEMM, fp16 2-pass (unchanged from R5).
// ---------------------------------------------------------------------------
static constexpr int GT = 8192;
static constexpr int GSTAGE = 3 * GT;
static constexpr int GEMM_SMEM = 2 * GSTAGE;

__global__ __launch_bounds__(256) void gemm_fp16x2_kernel(
    const __half* __restrict__ A, const __half* __restrict__ Bh,
    const __half* __restrict__ Bl, const float* __restrict__ bias,
    float* __restrict__ C, int M, int N, int K)
{
    extern __shared__ char smem[];
    const uint32_t sb = smem_u32(smem);
    const int tid  = threadIdx.x;
    const int wid  = tid >> 5;
    const int lane = tid & 31;
    const int bm = blockIdx.y * 128;
    const int bn = blockIdx.x * 128;
    const int m0 = (wid >> 2) * 64;
    const int n0 = (wid & 3) * 32;

    float acc[4][4][4];
#pragma unroll
    for (int i = 0; i < 4; i++)
#pragma unroll
        for (int j = 0; j < 4; j++)
#pragma unroll
            for (int r = 0; r < 4; r++) acc[i][j][r] = 0.0f;

    const int nchunk = K >> 5;

    auto load_stage = [&](int c, int stage) {
        const int k0 = c << 5;
        const uint32_t sbase = sb + stage * GSTAGE;
#pragma unroll
        for (int t = 0; t < 6; t++) {
            int op   = tid + t * 256;
            int tile = op >> 9;
            int idx  = op & 511;
            int row  = idx >> 2;
            int ch   = idx & 3;
            const __half* src = (tile == 0) ? A : (tile == 1) ? Bh : Bl;
            int grow = ((tile == 0) ? bm : bn) + row;
            const void* g = src + (size_t)grow * K + k0 + ch * 8;
            uint32_t saddr = sbase + (uint32_t)tile * GT + sw_off(row, ch);
            CP_ASYNC16(saddr, g);
        }
        CP_COMMIT();
    };

    const int rA = ((lane >> 3) & 1) * 8 + (lane & 7);
    const int cA = (lane >> 4);
    const int rB = ((lane >> 4) & 1) * 8 + (lane & 7);
    const int cB = ((lane >> 3) & 1);

    load_stage(0, 0);

    for (int c = 0; c < nchunk; c++) {
        if (c + 1 < nchunk) { load_stage(c + 1, (c + 1) & 1); CP_WAIT(1); }
        else                { CP_WAIT(0); }
        __syncthreads();

        const uint32_t sbase = sb + (c & 1) * GSTAGE;
#pragma unroll
        for (int s = 0; s < 2; s++) {
            uint32_t af[4][4], bhf[2][4], blf[2][4];
#pragma unroll
            for (int i = 0; i < 4; i++) {
                uint32_t off = sw_off(m0 + i * 16 + rA, 2 * s + cA);
                LDSM_X4(af[i], sbase + off);
            }
#pragma unroll
            for (int j2 = 0; j2 < 2; j2++) {
                uint32_t off = sw_off(n0 + j2 * 16 + rB, 2 * s + cB);
                LDSM_X4(bhf[j2], sbase + GT + off);
                LDSM_X4(blf[j2], sbase + 2 * GT + off);
            }
#pragma unroll
            for (int i = 0; i < 4; i++)
#pragma unroll
                for (int j2 = 0; j2 < 2; j2++)
#pragma unroll
                    for (int jj = 0; jj < 2; jj++) {
                        float* cc = acc[i][j2 * 2 + jj];
                        MMA_FP16(cc, af[i], bhf[j2][jj * 2], bhf[j2][jj * 2 + 1]);
                        MMA_FP16(cc, af[i], blf[j2][jj * 2], blf[j2][jj * 2 + 1]);
                    }
        }
        __syncthreads();
    }

    const float inv32 = 0.03125f;
#pragma unroll
    for (int i = 0; i < 4; i++) {
#pragma unroll
        for (int j = 0; j < 4; j++) {
            int row = bm + m0 + i * 16 + (lane >> 2);
            int col = bn + n0 + j * 8 + (lane & 3) * 2;
            float bx = 0.0f, by = 0.0f;
            if (bias) { bx = bias[col]; by = bias[col + 1]; }
            float2 v0 = make_float2(acc[i][j][0] * inv32 + bx,
                                    acc[i][j][1] * inv32 + by);
            float2 v1 = make_float2(acc[i][j][2] * inv32 + bx,
                                    acc[i][j][3] * inv32 + by);
            *(float2*)(C + (size_t)row * N + col) = v0;
            *(float2*)(C + (size_t)(row + 8) * N + col) = v1;
        }
    }
}

// ---------------------------------------------------------------------------
// RoPE on Q -> fp16 hi/lo (UNSCALED), head-major [b,h,s,d].
// ---------------------------------------------------------------------------
__global__ __launch_bounds__(256) void rope_q_split_kernel(
    const float* __restrict__ Q, const float* __restrict__ cosT,
    const float* __restrict__ sinT, __half* __restrict__ qh,
    __half* __restrict__ ql)
{
    const int row = blockIdx.x;
    const int b = row >> 11;
    const int s = row & (Ss - 1);
    const float* qrow = Q + (size_t)row * HID;
    const float* cr = cosT + (size_t)s * HD;
    const float* sr = sinT + (size_t)s * HD;
    for (int p = threadIdx.x; p < NH * 32; p += blockDim.x) {
        const int h = p >> 5;
        const int d = (p & 31) * 2;
        const float* q = qrow + h * HD;
        float lo0 = q[d],      lo1 = q[d + 1];
        float hi0 = q[d + 64], hi1 = q[d + 65];
        float e0 = lo0 * cr[d]     - hi0 * sr[d];
        float e1 = lo1 * cr[d + 1] - hi1 * sr[d + 1];
        float f0 = hi0 * cr[d + 64] + lo0 * sr[d + 64];
        float f1 = hi1 * cr[d + 65] + lo1 * sr[d + 65];
        size_t ob = ((size_t)(b * NH + h) * Ss + s) * HD;
        uint32_t ph, pl;
        hsplit2(e0, e1, ph, pl);
        *(uint32_t*)(qh + ob + d) = ph; *(uint32_t*)(ql + ob + d) = pl;
        hsplit2(f0, f1, ph, pl);
        *(uint32_t*)(qh + ob + d + 64) = ph; *(uint32_t*)(ql + ob + d + 64) = pl;
    }
}

// ---------------------------------------------------------------------------
// RoPE on K + V copy -> single fp16, head-major [b,kv,s,d].
// ---------------------------------------------------------------------------
__global__ __launch_bounds__(256) void rope_kv_split_kernel(
    const float* __restrict__ KV, const float* __restrict__ cosT,
    const float* __restrict__ sinT,
    __half* __restrict__ kF, __half* __restrict__ vF)
{
    const int row = blockIdx.x;
    const int b = row >> 11;
    const int s = row & (Ss - 1);
    const float* kvrow = KV + (size_t)row * KVW;
    const float* cr = cosT + (size_t)s * HD;
    const float* sr = sinT + (size_t)s * HD;
    for (int p = threadIdx.x; p < NKV * 32; p += blockDim.x) {
        const int kv = p >> 5;
        const int d = (p & 31) * 2;
        const float* k = kvrow + kv * (2 * HD);
        const float* v = k + HD;
        float lo0 = k[d],      lo1 = k[d + 1];
        float hi0 = k[d + 64], hi1 = k[d + 65];
        float e0 = lo0 * cr[d]     - hi0 * sr[d];
        float e1 = lo1 * cr[d + 1] - hi1 * sr[d + 1];
        float f0 = hi0 * cr[d + 64] + lo0 * sr[d + 64];
        float f1 = hi1 * cr[d + 65] + lo1 * sr[d + 65];
        size_t ob = ((size_t)(b * NKV + kv) * Ss + s) * HD;
        *(__half2*)(kF + ob + d)      = __floats2half2_rn(e0, e1);
        *(__half2*)(kF + ob + d + 64) = __floats2half2_rn(f0, f1);
        *(__half2*)(vF + ob + d)      = __floats2half2_rn(v[d], v[d + 1]);
        *(__half2*)(vF + ob + d + 64) = __floats2half2_rn(v[d + 64], v[d + 65]);
    }
}

// ---------------------------------------------------------------------------
// Flash attention, fp16 2-pass. Grid (S/64, NH, B), 128 threads (4 warps).
// smem tiles: Qh, Ql, K, V (each 64x128 fp16 = 16KB) -> 64KB, 3 CTAs/SM.
// Scores scaled by 1/sqrt(HD) post-MMA; P split x512 in registers for PV.
// ---------------------------------------------------------------------------
static constexpr int AT = 64 * 256;
static constexpr int ATTN_SMEM = 4 * AT;   // 64 KB

__global__ __launch_bounds__(128) void flash_attn_mma_kernel(
    const __half* __restrict__ qh, const __half* __restrict__ ql,
    const __half* __restrict__ kF, const __half* __restrict__ vF,
    __half* __restrict__ atF)
{
    extern __shared__ char smem[];
    const uint32_t sb = smem_u32(smem);
    const int qt = blockIdx.x;
    const int h  = blockIdx.y;
    const int b  = blockIdx.z;
    const int kvh = h >> 2;
    const int tid = threadIdx.x;
    const int wid = tid >> 5;
    const int lane = tid & 31;
    const int r0 = wid * 16;
    const float scale = 0.08838834764831845f;  // 1/sqrt(128)

    const int rA = (lane & 7) + ((lane >> 3) & 1) * 8;
    const int cA = lane >> 4;
    const int rB = (lane & 7) + ((lane >> 4) & 1) * 8;
    const int cB = (lane >> 3) & 1;

    const size_t qbase = ((size_t)(b * NH + h) * Ss + (size_t)qt * 64) * HD;
    for (int idx = tid; idx < 1024; idx += 128) {
        int r = idx >> 4, ch = idx & 15;
        uint32_t so = sw256(r, ch);
        const size_t g = qbase + (size_t)r * HD + ch * 8;
        CP_ASYNC16(sb + so, qh + g);
        CP_ASYNC16(sb + AT + so, ql + g);
    }
    CP_COMMIT();

    float oacc[16][4];
#pragma unroll
    for (int i = 0; i < 16; i++)
#pragma unroll
        for (int j = 0; j < 4; j++) oacc[i][j] = 0.0f;
    float mrow[2] = {-1e30f, -1e30f};
    float lrow[2] = {0.0f, 0.0f};

    const size_t kvbase = ((size_t)(b * NKV + kvh) * Ss) * HD;

    CP_WAIT(0);
    __syncthreads();

    for (int kt = 0; kt <= qt; kt++) {
        const size_t kb = kvbase + (size_t)kt * 64 * HD;
        for (int idx = tid; idx < 1024; idx += 128) {
            int r = idx >> 4, ch = idx & 15;
            uint32_t so = sw256(r, ch);
            const size_t g = kb + (size_t)r * HD + ch * 8;
            CP_ASYNC16(sb + 2 * AT + so, kF + g);
            CP_ASYNC16(sb + 3 * AT + so, vF + g);
        }
        CP_COMMIT();
        CP_WAIT(0);
        __syncthreads();

        // ---- S = Q K^T (2-pass: Qh + Ql vs single K) ----
        float sacc[8][4];
#pragma unroll
        for (int i = 0; i < 8; i++)
#pragma unroll
            for (int j = 0; j < 4; j++) sacc[i][j] = 0.0f;

#pragma unroll
        for (int kc = 0; kc < 8; kc++) {
            uint32_t ah[4], al[4];
            uint32_t offA = sw256(r0 + rA, 2 * kc + cA);
            LDSM_X4(ah, sb + offA);
            LDSM_X4(al, sb + AT + offA);
#pragma unroll
            for (int nbp = 0; nbp < 4; nbp++) {
                uint32_t bk[4];
                uint32_t offB = sw256(nbp * 16 + rB, 2 * kc + cB);
                LDSM_X4(bk, sb + 2 * AT + offB);
#pragma unroll
                for (int jj = 0; jj < 2; jj++) {
                    float* cc = sacc[nbp * 2 + jj];
                    MMA_FP16(cc, ah, bk[jj * 2], bk[jj * 2 + 1]);
                    MMA_FP16(cc, al, bk[jj * 2], bk[jj * 2 + 1]);
                }
            }
        }

        // apply softmax scale post-MMA
#pragma unroll
        for (int nb = 0; nb < 8; nb++) {
#pragma unroll
            for (int j = 0; j < 4; j++) sacc[nb][j] *= scale;
        }

        // ---- causal mask on diagonal tile ----
        if (kt == qt) {
            const int rl = lane >> 2;
            const int c0 = (lane & 3) * 2;
#pragma unroll
            for (int nb = 0; nb < 8; nb++) {
#pragma unroll
                for (int j = 0; j < 4; j++) {
                    int col = nb * 8 + c0 + (j & 1);
                    int row = r0 + rl + (j >> 1) * 8;
                    if (col > row) sacc[nb][j] = -1e30f;
                }
            }
        }

        // ---- online softmax (2 rows per lane) ----
        float mx0 = -1e30f, mx1 = -1e30f;
#pragma unroll
        for (int nb = 0; nb < 8; nb++) {
            mx0 = fmaxf(mx0, fmaxf(sacc[nb][0], sacc[nb][1]));
            mx1 = fmaxf(mx1, fmaxf(sacc[nb][2], sacc[nb][3]));
        }
        mx0 = fmaxf(mx0, __shfl_xor_sync(0xffffffffu, mx0, 1));
        mx0 = fmaxf(mx0, __shfl_xor_sync(0xffffffffu, mx0, 2));
        mx1 = fmaxf(mx1, __shfl_xor_sync(0xffffffffu, mx1, 1));
        mx1 = fmaxf(mx1, __shfl_xor_sync(0xffffffffu, mx1, 2));
        float mn0 = fmaxf(mrow[0], mx0);
        float mn1 = fmaxf(mrow[1], mx1);
        float fac0 = __expf(mrow[0] - mn0);
        float fac1 = __expf(mrow[1] - mn1);
        mrow[0] = mn0; mrow[1] = mn1;
        lrow[0] *= fac0; lrow[1] *= fac1;
#pragma unroll
        for (int nb = 0; nb < 8; nb++) {
            float p0 = __expf(sacc[nb][0] - mn0);
            float p1 = __expf(sacc[nb][1] - mn0);
            float p2 = __expf(sacc[nb][2] - mn1);
            float p3 = __expf(sacc[nb][3] - mn1);
            lrow[0] += p0 + p1; lrow[1] += p2 + p3;
            sacc[nb][0] = p0 * 512.0f; sacc[nb][1] = p1 * 512.0f;
            sacc[nb][2] = p2 * 512.0f; sacc[nb][3] = p3 * 512.0f;
        }
#pragma unroll
        for (int db = 0; db < 16; db++) {
            oacc[db][0] *= fac0; oacc[db][1] *= fac0;
            oacc[db][2] *= fac1; oacc[db][3] *= fac1;
        }

        // ---- pack 512*P into fp16 hi/lo A-fragments ----
        uint32_t aPh[4][4], aPl[4][4];
#pragma unroll
        for (int kc2 = 0; kc2 < 4; kc2++) {
            hsplit2(sacc[2 * kc2][0],     sacc[2 * kc2][1],     aPh[kc2][0], aPl[kc2][0]);
            hsplit2(sacc[2 * kc2][2],     sacc[2 * kc2][3],     aPh[kc2][1], aPl[kc2][1]);
            hsplit2(sacc[2 * kc2 + 1][0], sacc[2 * kc2 + 1][1], aPh[kc2][2], aPl[kc2][2]);
            hsplit2(sacc[2 * kc2 + 1][2], sacc[2 * kc2 + 1][3], aPh[kc2][3], aPl[kc2][3]);
        }

        // ---- O += P V (2-pass: Ph + Pl vs single V) ----
#pragma unroll
        for (int kc2 = 0; kc2 < 4; kc2++) {
#pragma unroll
            for (int dbp = 0; dbp < 8; dbp++) {
                uint32_t vf[4];
                uint32_t offV = sw256(kc2 * 16 + rA, 2 * dbp + cA);
                LDSM_X4_T(vf, sb + 3 * AT + offV);
#pragma unroll
                for (int jj = 0; jj < 2; jj++) {
                    float* cc = oacc[dbp * 2 + jj];
                    MMA_FP16(cc, aPh[kc2], vf[jj * 2], vf[jj * 2 + 1]);
                    MMA_FP16(cc, aPl[kc2], vf[jj * 2], vf[jj * 2 + 1]);
                }
            }
        }
        __syncthreads();
    }

    // ---- finalize (oacc holds 512 * sum(pv); fold /512 into 1/l) ----
    lrow[0] += __shfl_xor_sync(0xffffffffu, lrow[0], 1);
    lrow[0] += __shfl_xor_sync(0xffffffffu, lrow[0], 2);
    lrow[1] += __shfl_xor_sync(0xffffffffu, lrow[1], 1);
    lrow[1] += __shfl_xor_sync(0xffffffffu, lrow[1], 2);
    const float inv0 = 1.0f / (512.0f * lrow[0]);
    const float inv1 = 1.0f / (512.0f * lrow[1]);
    const int rl = lane >> 2;
    const int c0 = (lane & 3) * 2;
    const size_t row0 = (size_t)(b * Ss + qt * 64 + r0 + rl) * HID + h * HD;
    const size_t row1 = row0 + (size_t)8 * HID;
#pragma unroll
    for (int db = 0; db < 16; db++) {
        const int col = db * 8 + c0;
        __half2 a = __floats2half2_rn(oacc[db][0] * inv0, oacc[db][1] * inv0);
        __half2 c = __floats2half2_rn(oacc[db][2] * inv1, oacc[db][3] * inv1);
        *(__half2*)(atF + row0 + col) = a;
        *(__half2*)(atF + row1 + col) = c;
    }
}

// ---------------------------------------------------------------------------
// Launch
// ---------------------------------------------------------------------------
extern "C" void kernel_launch(void* const* d_in, const int* in_sizes, int n_in,
                              void* d_out, int out_size)
{
    const float* hidden = (const float*)d_in[0];
    const float* cosT = (const float*)d_in[2];
    const float* sinT = (const float*)d_in[3];
    const float* Wq   = (const float*)d_in[4];
    const float* Wkv  = (const float*)d_in[5];
    const float* Wd   = (const float*)d_in[6];
    const float* bd   = (const float*)d_in[7];
    float* out = (float*)d_out;

    float *Qb, *KVb;
    cudaGetSymbolAddress((void**)&Qb,  g_Q);
    cudaGetSymbolAddress((void**)&KVb, g_KV);

    __half *hidF, *wqH, *wqL, *wkvH, *wkvL, *wdH, *wdL, *atF;
    cudaGetSymbolAddress((void**)&hidF, g_hidF);
    cudaGetSymbolAddress((void**)&wqH,  g_WqH);
    cudaGetSymbolAddress((void**)&wqL,  g_WqL);
    cudaGetSymbolAddress((void**)&wkvH, g_WkvH);
    cudaGetSymbolAddress((void**)&wkvL, g_WkvL);
    cudaGetSymbolAddress((void**)&wdH,  g_WdH);
    cudaGetSymbolAddress((void**)&wdL,  g_WdL);
    cudaGetSymbolAddress((void**)&atF,  g_atF);

    __half *qh, *ql, *kF, *vF;
    cudaGetSymbolAddress((void**)&qh, g_qh);
    cudaGetSymbolAddress((void**)&ql, g_ql);
    cudaGetSymbolAddress((void**)&kF, g_kF);
    cudaGetSymbolAddress((void**)&vF, g_vF);

    cudaFuncSetAttribute(gemm_fp16x2_kernel,
                         cudaFuncAttributeMaxDynamicSharedMemorySize, GEMM_SMEM);
    cudaFuncSetAttribute(flash_attn_mma_kernel,
                         cudaFuncAttributeMaxDynamicSharedMemorySize, ATTN_SMEM);

    const int n_hid = M_TOK * HID / 4;
    const int n_wkv = KVW * HID / 4;
    conv_fp16_kernel  <<<2048, 256>>>(hidden, hidF, n_hid);
    conv_wsplit_kernel<<<2048, 256>>>(Wq,  wqH,  wqL,  n_hid);
    conv_wsplit_kernel<<<2048, 256>>>(Wkv, wkvH, wkvL, n_wkv);
    conv_wsplit_kernel<<<2048, 256>>>(Wd,  wdH,  wdL,  n_hid);

    gemm_fp16x2_kernel<<<dim3(HID / 128, M_TOK / 128), 256, GEMM_SMEM>>>(
        hidF, wqH, wqL, nullptr, Qb, M_TOK, HID, HID);
    gemm_fp16x2_kernel<<<dim3(KVW / 128, M_TOK / 128), 256, GEMM_SMEM>>>(
        hidF, wkvH, wkvL, nullptr, KVb, M_TOK, KVW, HID);

    rope_q_split_kernel<<<M_TOK, 256>>>(Qb, cosT, sinT, qh, ql);
    rope_kv_split_kernel<<<M_TOK, 256>>>(KVb, cosT, sinT, kF, vF);

    flash_attn_mma_kernel<<<dim3(Ss / 64, NH, Bb), 128, ATTN_SMEM>>>(
        qh, ql, kF, vF, atF);

    gemm_fp16x2_kernel<<<dim3(HID / 128, M_TOK / 128), 256, GEMM_SMEM>>>(
        atF, wdH, wdL, bd, out, M_TOK, HID, HID);
}

// round 8
// speedup vs baseline: 5.0818x; 1.0378x over previous
#include <cuda_runtime.h>
#include <cuda_bf16.h>
#include <cuda_fp16.h>
#include <math.h>
#include <stdint.h>

// ---------------------------------------------------------------------------
// TeleChat2 attention block, R7.
// Projection GEMMs: fp16 1-pass (activations fp16, weights fp16 x32).
// Flash attention: fp16 2-pass QK^T (Q hi/lo), softmax via ex2.approx.f16x2
//   (log2-domain), PV 1-pass with P direct from the f16x2 exp.
// ---------------------------------------------------------------------------

static constexpr int Bb  = 2;
static constexpr int Ss  = 2048;
static constexpr int HID = 4096;
static constexpr int NH  = 32;
static constexpr int NKV = 8;
static constexpr int HD  = 128;
static constexpr int M_TOK = Bb * Ss;
static constexpr int KVW   = 2 * NKV * HD;

// fp32 scratch (projection outputs)
__device__ float g_Q [(size_t)M_TOK * HID];
__device__ float g_KV[(size_t)M_TOK * KVW];

// fp16 operands
__device__ __half g_hidF [(size_t)M_TOK * HID];
__device__ __half g_WqF  [(size_t)HID * HID];
__device__ __half g_WkvF [(size_t)KVW * HID];
__device__ __half g_WdF  [(size_t)HID * HID];
__device__ __half g_atF  [(size_t)M_TOK * HID];

// fp16 attention operands (head-major)
__device__ __half g_qh[(size_t)M_TOK * HID];        // roped Q hi (unscaled)
__device__ __half g_ql[(size_t)M_TOK * HID];        // roped Q lo
__device__ __half g_kF[(size_t)Bb * NKV * Ss * HD]; // roped K
__device__ __half g_vF[(size_t)Bb * NKV * Ss * HD]; // V

// ---------------------------------------------------------------------------
// helpers
// ---------------------------------------------------------------------------
__device__ __forceinline__ uint32_t smem_u32(const void* p) {
    uint32_t a;
    asm("{ .reg .u64 t; cvta.to.shared.u64 t, %1; cvt.u32.u64 %0, t; }"
        : "=r"(a) : "l"(p));
    return a;
}
__device__ __forceinline__ uint32_t sw_off(int row, int chunk) {
    int unit = ((row & 1) * 4 + chunk) ^ ((row >> 1) & 7);
    return (uint32_t)((row >> 1) * 128 + unit * 16);
}
__device__ __forceinline__ uint32_t sw256(int row, int chunk) {
    return (uint32_t)(row * 256 + (((chunk ^ row) & 7) | (chunk & 8)) * 16);
}

#define LDSM_X4(r, addr) \
    asm volatile("ldmatrix.sync.aligned.m8n8.x4.shared.b16 {%0,%1,%2,%3}, [%4];" \
        : "=r"((r)[0]), "=r"((r)[1]), "=r"((r)[2]), "=r"((r)[3]) : "r"(addr))
#define LDSM_X4_T(r, addr) \
    asm volatile("ldmatrix.sync.aligned.m8n8.x4.trans.shared.b16 {%0,%1,%2,%3}, [%4];" \
        : "=r"((r)[0]), "=r"((r)[1]), "=r"((r)[2]), "=r"((r)[3]) : "r"(addr))

#define MMA_FP16(c, a, b0v, b1v) \
    asm volatile("mma.sync.aligned.m16n8k16.row.col.f32.f16.f16.f32 " \
        "{%0,%1,%2,%3}, {%4,%5,%6,%7}, {%8,%9}, {%0,%1,%2,%3};" \
        : "+f"((c)[0]), "+f"((c)[1]), "+f"((c)[2]), "+f"((c)[3]) \
        : "r"((a)[0]), "r"((a)[1]), "r"((a)[2]), "r"((a)[3]), "r"(b0v), "r"(b1v))

#define CP_ASYNC16(saddr, gptr) \
    asm volatile("cp.async.cg.shared.global [%0], [%1], 16;" \
        :: "r"(saddr), "l"(gptr) : "memory")
#define CP_COMMIT() asm volatile("cp.async.commit_group;" ::: "memory")
#define CP_WAIT(n)  asm volatile("cp.async.wait_group %0;" :: "n"(n) : "memory")

#define EX2_F16X2(d, s) \
    asm("ex2.approx.f16x2 %0, %1;" : "=r"(d) : "r"(s))
#define EX2_F32(d, s) \
    asm("ex2.approx.f32 %0, %1;" : "=f"(d) : "f"(s))

__device__ __forceinline__ void hsplit2(float x, float y,
                                        uint32_t& hi, uint32_t& lo) {
    __half hx = __float2half_rn(x);
    __half hy = __float2half_rn(y);
    __half lx = __float2half_rn(x - __half2float(hx));
    __half ly = __float2half_rn(y - __half2float(hy));
    __half2 h2(hx, hy), l2(lx, ly);
    hi = *(uint32_t*)&h2; lo = *(uint32_t*)&l2;
}

// ---------------------------------------------------------------------------
// fp32 -> fp16 (activations)
// ---------------------------------------------------------------------------
__global__ __launch_bounds__(256) void conv_fp16_kernel(
    const float* __restrict__ in, __half* __restrict__ out, int n4)
{
    int i = blockIdx.x * blockDim.x + threadIdx.x;
    int stride = gridDim.x * blockDim.x;
    const float4* in4 = (const float4*)in;
    __half2* o2 = (__half2*)out;
    for (; i < n4; i += stride) {
        float4 v = in4[i];
        o2[2 * i]     = __floats2half2_rn(v.x, v.y);
        o2[2 * i + 1] = __floats2half2_rn(v.z, v.w);
    }
}

// ---------------------------------------------------------------------------
// fp32 weights -> fp16 of 32*W (single rounding)
// ---------------------------------------------------------------------------
__global__ __launch_bounds__(256) void conv_wscale_kernel(
    const float* __restrict__ in, __half* __restrict__ out, int n4)
{
    int i = blockIdx.x * blockDim.x + threadIdx.x;
    int stride = gridDim.x * blockDim.x;
    const float4* in4 = (const float4*)in;
    __half2* o2 = (__half2*)out;
    for (; i < n4; i += stride) {
        float4 v = in4[i];
        o2[2 * i]     = __floats2half2_rn(v.x * 32.0f, v.y * 32.0f);
        o2[2 * i + 1] = __floats2half2_rn(v.z * 32.0f, v.w * 32.0f);
    }
}

// ---------------------------------------------------------------------------
// Tensor-core GEMM, fp16 1-pass: C[m,n] = (1/32) * sum_k A[m,k]*W[n,k] (+bias)
// CTA tile 128x128, BK=32, 256 threads = 8 warps (2m x 4n).
// smem per stage: A 8KB + B 8KB = 16KB, double-buffered.
// ---------------------------------------------------------------------------
static constexpr int GT = 8192;
static constexpr int GSTAGE = 2 * GT;            // 16 KB
static constexpr int GEMM_SMEM = 2 * GSTAGE;     // 32 KB

__global__ __launch_bounds__(256) void gemm_fp16_kernel(
    const __half* __restrict__ A, const __half* __restrict__ B,
    const float* __restrict__ bias, float* __restrict__ C,
    int M, int N, int K)
{
    extern __shared__ char smem[];
    const uint32_t sb = smem_u32(smem);
    const int tid  = threadIdx.x;
    const int wid  = tid >> 5;
    const int lane = tid & 31;
    const int bm = blockIdx.y * 128;
    const int bn = blockIdx.x * 128;
    const int m0 = (wid >> 2) * 64;
    const int n0 = (wid & 3) * 32;

    float acc[4][4][4];
#pragma unroll
    for (int i = 0; i < 4; i++)
#pragma unroll
        for (int j = 0; j < 4; j++)
#pragma unroll
            for (int r = 0; r < 4; r++) acc[i][j][r] = 0.0f;

    const int nchunk = K >> 5;

    auto load_stage = [&](int c, int stage) {
        const int k0 = c << 5;
        const uint32_t sbase = sb + stage * GSTAGE;
#pragma unroll
        for (int t = 0; t < 4; t++) {
            int op   = tid + t * 256;      // 0..1023
            int tile = op >> 9;            // 0 A, 1 B
            int idx  = op & 511;
            int row  = idx >> 2;
            int ch   = idx & 3;
            const __half* src = (tile == 0) ? A : B;
            int grow = ((tile == 0) ? bm : bn) + row;
            const void* g = src + (size_t)grow * K + k0 + ch * 8;
            uint32_t saddr = sbase + (uint32_t)tile * GT + sw_off(row, ch);
            CP_ASYNC16(saddr, g);
        }
        CP_COMMIT();
    };

    const int rA = ((lane >> 3) & 1) * 8 + (lane & 7);
    const int cA = (lane >> 4);
    const int rB = ((lane >> 4) & 1) * 8 + (lane & 7);
    const int cB = ((lane >> 3) & 1);

    load_stage(0, 0);

    for (int c = 0; c < nchunk; c++) {
        if (c + 1 < nchunk) { load_stage(c + 1, (c + 1) & 1); CP_WAIT(1); }
        else                { CP_WAIT(0); }
        __syncthreads();

        const uint32_t sbase = sb + (c & 1) * GSTAGE;
#pragma unroll
        for (int s = 0; s < 2; s++) {
            uint32_t af[4][4], bf[2][4];
#pragma unroll
            for (int i = 0; i < 4; i++) {
                uint32_t off = sw_off(m0 + i * 16 + rA, 2 * s + cA);
                LDSM_X4(af[i], sbase + off);
            }
#pragma unroll
            for (int j2 = 0; j2 < 2; j2++) {
                uint32_t off = sw_off(n0 + j2 * 16 + rB, 2 * s + cB);
                LDSM_X4(bf[j2], sbase + GT + off);
            }
#pragma unroll
            for (int i = 0; i < 4; i++)
#pragma unroll
                for (int j2 = 0; j2 < 2; j2++)
#pragma unroll
                    for (int jj = 0; jj < 2; jj++) {
                        float* cc = acc[i][j2 * 2 + jj];
                        MMA_FP16(cc, af[i], bf[j2][jj * 2], bf[j2][jj * 2 + 1]);
                    }
        }
        __syncthreads();
    }

    const float inv32 = 0.03125f;
#pragma unroll
    for (int i = 0; i < 4; i++) {
#pragma unroll
        for (int j = 0; j < 4; j++) {
            int row = bm + m0 + i * 16 + (lane >> 2);
            int col = bn + n0 + j * 8 + (lane & 3) * 2;
            float bx = 0.0f, by = 0.0f;
            if (bias) { bx = bias[col]; by = bias[col + 1]; }
            float2 v0 = make_float2(acc[i][j][0] * inv32 + bx,
                                    acc[i][j][1] * inv32 + by);
            float2 v1 = make_float2(acc[i][j][2] * inv32 + bx,
                                    acc[i][j][3] * inv32 + by);
            *(float2*)(C + (size_t)row * N + col) = v0;
            *(float2*)(C + (size_t)(row + 8) * N + col) = v1;
        }
    }
}

// ---------------------------------------------------------------------------
// RoPE on Q -> fp16 hi/lo (UNSCALED), head-major [b,h,s,d].
// ---------------------------------------------------------------------------
__global__ __launch_bounds__(256) void rope_q_split_kernel(
    const float* __restrict__ Q, const float* __restrict__ cosT,
    const float* __restrict__ sinT, __half* __restrict__ qh,
    __half* __restrict__ ql)
{
    const int row = blockIdx.x;
    const int b = row >> 11;
    const int s = row & (Ss - 1);
    const float* qrow = Q + (size_t)row * HID;
    const float* cr = cosT + (size_t)s * HD;
    const float* sr = sinT + (size_t)s * HD;
    for (int p = threadIdx.x; p < NH * 32; p += blockDim.x) {
        const int h = p >> 5;
        const int d = (p & 31) * 2;
        const float* q = qrow + h * HD;
        float lo0 = q[d],      lo1 = q[d + 1];
        float hi0 = q[d + 64], hi1 = q[d + 65];
        float e0 = lo0 * cr[d]     - hi0 * sr[d];
        float e1 = lo1 * cr[d + 1] - hi1 * sr[d + 1];
        float f0 = hi0 * cr[d + 64] + lo0 * sr[d + 64];
        float f1 = hi1 * cr[d + 65] + lo1 * sr[d + 65];
        size_t ob = ((size_t)(b * NH + h) * Ss + s) * HD;
        uint32_t ph, pl;
        hsplit2(e0, e1, ph, pl);
        *(uint32_t*)(qh + ob + d) = ph; *(uint32_t*)(ql + ob + d) = pl;
        hsplit2(f0, f1, ph, pl);
        *(uint32_t*)(qh + ob + d + 64) = ph; *(uint32_t*)(ql + ob + d + 64) = pl;
    }
}

// ---------------------------------------------------------------------------
// RoPE on K + V copy -> single fp16, head-major [b,kv,s,d].
// ---------------------------------------------------------------------------
__global__ __launch_bounds__(256) void rope_kv_split_kernel(
    const float* __restrict__ KV, const float* __restrict__ cosT,
    const float* __restrict__ sinT,
    __half* __restrict__ kF, __half* __restrict__ vF)
{
    const int row = blockIdx.x;
    const int b = row >> 11;
    const int s = row & (Ss - 1);
    const float* kvrow = KV + (size_t)row * KVW;
    const float* cr = cosT + (size_t)s * HD;
    const float* sr = sinT + (size_t)s * HD;
    for (int p = threadIdx.x; p < NKV * 32; p += blockDim.x) {
        const int kv = p >> 5;
        const int d = (p & 31) * 2;
        const float* k = kvrow + kv * (2 * HD);
        const float* v = k + HD;
        float lo0 = k[d],      lo1 = k[d + 1];
        float hi0 = k[d + 64], hi1 = k[d + 65];
        float e0 = lo0 * cr[d]     - hi0 * sr[d];
        float e1 = lo1 * cr[d + 1] - hi1 * sr[d + 1];
        float f0 = hi0 * cr[d + 64] + lo0 * sr[d + 64];
        float f1 = hi1 * cr[d + 65] + lo1 * sr[d + 65];
        size_t ob = ((size_t)(b * NKV + kv) * Ss + s) * HD;
        *(__half2*)(kF + ob + d)      = __floats2half2_rn(e0, e1);
        *(__half2*)(kF + ob + d + 64) = __floats2half2_rn(f0, f1);
        *(__half2*)(vF + ob + d)      = __floats2half2_rn(v[d], v[d + 1]);
        *(__half2*)(vF + ob + d + 64) = __floats2half2_rn(v[d + 64], v[d + 65]);
    }
}

// ---------------------------------------------------------------------------
// Flash attention: QK^T fp16 2-pass; softmax in log2 domain via
// ex2.approx.f16x2; PV fp16 1-pass (P straight from the f16 exp).
// Grid (S/64, NH, B), 128 threads (4 warps); smem Qh,Ql,K,V = 64 KB.
// ---------------------------------------------------------------------------
static constexpr int AT = 64 * 256;
static constexpr int ATTN_SMEM = 4 * AT;   // 64 KB

__global__ __launch_bounds__(128) void flash_attn_mma_kernel(
    const __half* __restrict__ qh, const __half* __restrict__ ql,
    const __half* __restrict__ kF, const __half* __restrict__ vF,
    __half* __restrict__ atF)
{
    extern __shared__ char smem[];
    const uint32_t sb = smem_u32(smem);
    const int qt = blockIdx.x;
    const int h  = blockIdx.y;
    const int b  = blockIdx.z;
    const int kvh = h >> 2;
    const int tid = threadIdx.x;
    const int wid = tid >> 5;
    const int lane = tid & 31;
    const int r0 = wid * 16;
    // (1/sqrt(128)) * log2(e): scores go straight to the log2 domain
    const float kscale = 0.1275187952462235f;

    const int rA = (lane & 7) + ((lane >> 3) & 1) * 8;
    const int cA = lane >> 4;
    const int rB = (lane & 7) + ((lane >> 4) & 1) * 8;
    const int cB = (lane >> 3) & 1;

    const size_t qbase = ((size_t)(b * NH + h) * Ss + (size_t)qt * 64) * HD;
    for (int idx = tid; idx < 1024; idx += 128) {
        int r = idx >> 4, ch = idx & 15;
        uint32_t so = sw256(r, ch);
        const size_t g = qbase + (size_t)r * HD + ch * 8;
        CP_ASYNC16(sb + so, qh + g);
        CP_ASYNC16(sb + AT + so, ql + g);
    }
    CP_COMMIT();

    float oacc[16][4];
#pragma unroll
    for (int i = 0; i < 16; i++)
#pragma unroll
        for (int j = 0; j < 4; j++) oacc[i][j] = 0.0f;
    float mrow[2] = {-1e30f, -1e30f};
    float lrow[2] = {0.0f, 0.0f};

    const size_t kvbase = ((size_t)(b * NKV + kvh) * Ss) * HD;

    CP_WAIT(0);
    __syncthreads();

    for (int kt = 0; kt <= qt; kt++) {
        const size_t kb = kvbase + (size_t)kt * 64 * HD;
        for (int idx = tid; idx < 1024; idx += 128) {
            int r = idx >> 4, ch = idx & 15;
            uint32_t so = sw256(r, ch);
            const size_t g = kb + (size_t)r * HD + ch * 8;
            CP_ASYNC16(sb + 2 * AT + so, kF + g);
            CP_ASYNC16(sb + 3 * AT + so, vF + g);
        }
        CP_COMMIT();
        CP_WAIT(0);
        __syncthreads();

        // ---- S = Q K^T (2-pass: Qh + Ql vs single K) ----
        float sacc[8][4];
#pragma unroll
        for (int i = 0; i < 8; i++)
#pragma unroll
            for (int j = 0; j < 4; j++) sacc[i][j] = 0.0f;

#pragma unroll
        for (int kc = 0; kc < 8; kc++) {
            uint32_t ah[4], al[4];
            uint32_t offA = sw256(r0 + rA, 2 * kc + cA);
            LDSM_X4(ah, sb + offA);
            LDSM_X4(al, sb + AT + offA);
#pragma unroll
            for (int nbp = 0; nbp < 4; nbp++) {
                uint32_t bk[4];
                uint32_t offB = sw256(nbp * 16 + rB, 2 * kc + cB);
                LDSM_X4(bk, sb + 2 * AT + offB);
#pragma unroll
                for (int jj = 0; jj < 2; jj++) {
                    float* cc = sacc[nbp * 2 + jj];
                    MMA_FP16(cc, ah, bk[jj * 2], bk[jj * 2 + 1]);
                    MMA_FP16(cc, al, bk[jj * 2], bk[jj * 2 + 1]);
                }
            }
        }

        // scale into log2 domain
#pragma unroll
        for (int nb = 0; nb < 8; nb++) {
#pragma unroll
            for (int j = 0; j < 4; j++) sacc[nb][j] *= kscale;
        }

        // ---- causal mask on diagonal tile ----
        if (kt == qt) {
            const int rl = lane >> 2;
            const int c0 = (lane & 3) * 2;
#pragma unroll
            for (int nb = 0; nb < 8; nb++) {
#pragma unroll
                for (int j = 0; j < 4; j++) {
                    int col = nb * 8 + c0 + (j & 1);
                    int row = r0 + rl + (j >> 1) * 8;
                    if (col > row) sacc[nb][j] = -1e30f;
                }
            }
        }

        // ---- online softmax (log2 domain, 2 rows per lane) ----
        float mx0 = -1e30f, mx1 = -1e30f;
#pragma unroll
        for (int nb = 0; nb < 8; nb++) {
            mx0 = fmaxf(mx0, fmaxf(sacc[nb][0], sacc[nb][1]));
            mx1 = fmaxf(mx1, fmaxf(sacc[nb][2], sacc[nb][3]));
        }
        mx0 = fmaxf(mx0, __shfl_xor_sync(0xffffffffu, mx0, 1));
        mx0 = fmaxf(mx0, __shfl_xor_sync(0xffffffffu, mx0, 2));
        mx1 = fmaxf(mx1, __shfl_xor_sync(0xffffffffu, mx1, 1));
        mx1 = fmaxf(mx1, __shfl_xor_sync(0xffffffffu, mx1, 2));
        float mn0 = fmaxf(mrow[0], mx0);
        float mn1 = fmaxf(mrow[1], mx1);
        float fac0, fac1;
        EX2_F32(fac0, mrow[0] - mn0);
        EX2_F32(fac1, mrow[1] - mn1);
        mrow[0] = mn0; mrow[1] = mn1;
        lrow[0] *= fac0; lrow[1] *= fac1;

        // p = 2^(x - mn) via f16x2 MUFU; P lands directly in A-fragments
        uint32_t aP[4][4];
        uint32_t lh0 = 0, lh1 = 0;   // half2 accumulators
#pragma unroll
        for (int nb = 0; nb < 8; nb++) {
            __half2 h01 = __floats2half2_rn(sacc[nb][0] - mn0, sacc[nb][1] - mn0);
            __half2 h23 = __floats2half2_rn(sacc[nb][2] - mn1, sacc[nb][3] - mn1);
            uint32_t p01, p23;
            EX2_F16X2(p01, *(uint32_t*)&h01);
            EX2_F16X2(p23, *(uint32_t*)&h23);
            const int kc2 = nb >> 1;
            aP[kc2][(nb & 1) * 2 + 0] = p01;   // row r
            aP[kc2][(nb & 1) * 2 + 1] = p23;   // row r+8
            __half2 s0 = __hadd2(*(__half2*)&lh0, *(__half2*)&p01);
            __half2 s1 = __hadd2(*(__half2*)&lh1, *(__half2*)&p23);
            lh0 = *(uint32_t*)&s0; lh1 = *(uint32_t*)&s1;
        }
        {
            __half2 L0 = *(__half2*)&lh0;
            __half2 L1 = *(__half2*)&lh1;
            lrow[0] += __low2float(L0) + __high2float(L0);
            lrow[1] += __low2float(L1) + __high2float(L1);
        }
#pragma unroll
        for (int db = 0; db < 16; db++) {
            oacc[db][0] *= fac0; oacc[db][1] *= fac0;
            oacc[db][2] *= fac1; oacc[db][3] *= fac1;
        }

        // ---- O += P V (1-pass) ----
#pragma unroll
        for (int kc2 = 0; kc2 < 4; kc2++) {
#pragma unroll
            for (int dbp = 0; dbp < 8; dbp++) {
                uint32_t vf[4];
                uint32_t offV = sw256(kc2 * 16 + rA, 2 * dbp + cA);
                LDSM_X4_T(vf, sb + 3 * AT + offV);
#pragma unroll
                for (int jj = 0; jj < 2; jj++) {
                    float* cc = oacc[dbp * 2 + jj];
                    MMA_FP16(cc, aP[kc2], vf[jj * 2], vf[jj * 2 + 1]);
                }
            }
        }
        __syncthreads();
    }

    // ---- finalize ----
    lrow[0] += __shfl_xor_sync(0xffffffffu, lrow[0], 1);
    lrow[0] += __shfl_xor_sync(0xffffffffu, lrow[0], 2);
    lrow[1] += __shfl_xor_sync(0xffffffffu, lrow[1], 1);
    lrow[1] += __shfl_xor_sync(0xffffffffu, lrow[1], 2);
    const float inv0 = 1.0f / lrow[0];
    const float inv1 = 1.0f / lrow[1];
    const int rl = lane >> 2;
    const int c0 = (lane & 3) * 2;
    const size_t row0 = (size_t)(b * Ss + qt * 64 + r0 + rl) * HID + h * HD;
    const size_t row1 = row0 + (size_t)8 * HID;
#pragma unroll
    for (int db = 0; db < 16; db++) {
        const int col = db * 8 + c0;
        __half2 a = __floats2half2_rn(oacc[db][0] * inv0, oacc[db][1] * inv0);
        __half2 c = __floats2half2_rn(oacc[db][2] * inv1, oacc[db][3] * inv1);
        *(__half2*)(atF + row0 + col) = a;
        *(__half2*)(atF + row1 + col) = c;
    }
}

// ---------------------------------------------------------------------------
// Launch
// ---------------------------------------------------------------------------
extern "C" void kernel_launch(void* const* d_in, const int* in_sizes, int n_in,
                              void* d_out, int out_size)
{
    const float* hidden = (const float*)d_in[0];
    const float* cosT = (const float*)d_in[2];
    const float* sinT = (const float*)d_in[3];
    const float* Wq   = (const float*)d_in[4];
    const float* Wkv  = (const float*)d_in[5];
    const float* Wd   = (const float*)d_in[6];
    const float* bd   = (const float*)d_in[7];
    float* out = (float*)d_out;

    float *Qb, *KVb;
    cudaGetSymbolAddress((void**)&Qb,  g_Q);
    cudaGetSymbolAddress((void**)&KVb, g_KV);

    __half *hidF, *wqF, *wkvF, *wdF, *atF;
    cudaGetSymbolAddress((void**)&hidF, g_hidF);
    cudaGetSymbolAddress((void**)&wqF,  g_WqF);
    cudaGetSymbolAddress((void**)&wkvF, g_WkvF);
    cudaGetSymbolAddress((void**)&wdF,  g_WdF);
    cudaGetSymbolAddress((void**)&atF,  g_atF);

    __half *qh, *ql, *kF, *vF;
    cudaGetSymbolAddress((void**)&qh, g_qh);
    cudaGetSymbolAddress((void**)&ql, g_ql);
    cudaGetSymbolAddress((void**)&kF, g_kF);
    cudaGetSymbolAddress((void**)&vF, g_vF);

    cudaFuncSetAttribute(gemm_fp16_kernel,
                         cudaFuncAttributeMaxDynamicSharedMemorySize, GEMM_SMEM);
    cudaFuncSetAttribute(flash_attn_mma_kernel,
                         cudaFuncAttributeMaxDynamicSharedMemorySize, ATTN_SMEM);

    const int n_hid = M_TOK * HID / 4;
    const int n_wkv = KVW * HID / 4;
    conv_fp16_kernel  <<<2048, 256>>>(hidden, hidF, n_hid);
    conv_wscale_kernel<<<2048, 256>>>(Wq,  wqF,  n_hid);
    conv_wscale_kernel<<<2048, 256>>>(Wkv, wkvF, n_wkv);
    conv_wscale_kernel<<<2048, 256>>>(Wd,  wdF,  n_hid);

    gemm_fp16_kernel<<<dim3(HID / 128, M_TOK / 128), 256, GEMM_SMEM>>>(
        hidF, wqF, nullptr, Qb, M_TOK, HID, HID);
    gemm_fp16_kernel<<<dim3(KVW / 128, M_TOK / 128), 256, GEMM_SMEM>>>(
        hidF, wkvF, nullptr, KVb, M_TOK, KVW, HID);

    rope_q_split_kernel<<<M_TOK, 256>>>(Qb, cosT, sinT, qh, ql);
    rope_kv_split_kernel<<<M_TOK, 256>>>(KVb, cosT, sinT, kF, vF);

    flash_attn_mma_kernel<<<dim3(Ss / 64, NH, Bb), 128, ATTN_SMEM>>>(
        qh, ql, kF, vF, atF);

    gemm_fp16_kernel<<<dim3(HID / 128, M_TOK / 128), 256, GEMM_SMEM>>>(
        atF, wdF, bd, out, M_TOK, HID, HID);
}